// round 13
// baseline (speedup 1.0000x reference)
#include <cuda_runtime.h>
#include <cuda_bf16.h>
#include <math.h>
#include <stdint.h>

#define B_  4
#define NP  1024
#define ND  256
#define NT  1280
#define C_  1024
#define H_  16
#define DH  64
#define HID 2730
#define HIDP 2752
#define N12  (2*HID)       // 5460
#define N12I (2*HIDP)      // 5504 (43*128)
#define TOK  (B_*NT)   // 5120
#define PTOK (B_*NP)   // 4096
#define DTOK (B_*ND)   // 1024

// ---------------- fp32 scratch ----------------
constexpr size_t OFF_SILU = 0;
constexpr size_t OFF_ADA  = OFF_SILU + 4096;
constexpr size_t OFF_XAP  = OFF_ADA  + 49152;
constexpr size_t OFF_XAD  = OFF_XAP  + (size_t)PTOK*C_;
constexpr size_t OFF_B12P = OFF_XAD  + (size_t)DTOK*C_;
constexpr size_t OFF_B12D = OFF_B12P + N12I;
constexpr size_t OFF_END  = OFF_B12D + N12I;

__device__ __align__(16) float g_scratch[OFF_END];
__device__ int g_flags[B_];

// ---------------- bf16 scratch ----------------
constexpr size_t BO_XC    = 0;
constexpr size_t BO_ATTN  = BO_XC    + (size_t)TOK*C_;
constexpr size_t BO_H2P   = BO_ATTN  + (size_t)TOK*C_;
constexpr size_t BO_H2D   = BO_H2P   + (size_t)PTOK*C_;
constexpr size_t BO_GLP   = BO_H2D   + (size_t)DTOK*C_;
constexpr size_t BO_GLD   = BO_GLP   + (size_t)PTOK*HIDP;
constexpr size_t BO_QB    = BO_GLD   + (size_t)DTOK*HIDP;
constexpr size_t BO_KB    = BO_QB    + (size_t)TOK*C_;
constexpr size_t BO_VB    = BO_KB    + (size_t)TOK*C_;
constexpr size_t BO_WQKV  = BO_VB    + (size_t)TOK*C_;
constexpr size_t BO_WPROJ = BO_WQKV  + (size_t)C_*3*C_;
constexpr size_t BO_W12P  = BO_WPROJ + (size_t)C_*C_;
constexpr size_t BO_W12D  = BO_W12P  + (size_t)C_*N12I;
constexpr size_t BO_W3P   = BO_W12D  + (size_t)C_*N12I;
constexpr size_t BO_W3D   = BO_W3P   + (size_t)HIDP*C_;
constexpr size_t BO_END   = BO_W3D   + (size_t)HIDP*C_;

__device__ __align__(16) __nv_bfloat16 g_bf[BO_END];

// ---------------- prep ----------------
__global__ void prep_kernel(const float* __restrict__ c, const void* __restrict__ flags) {
    int i = blockIdx.x * blockDim.x + threadIdx.x;
    if (i < B_ * C_) {
        float v = c[i];
        g_scratch[OFF_SILU + i] = v / (1.f + expf(-v));
    }
    if (blockIdx.x == 0 && threadIdx.x == 0) {
        const int* pi = (const int*)flags;
        const float* pf = (const float*)flags;
        const unsigned char* pc = (const unsigned char*)flags;
        bool iok = true, fok = true;
        for (int b = 0; b < B_; b++) {
            int t = pi[b]; if (t != 0 && t != 1) iok = false;
            float f = pf[b]; if (f != 0.f && f != 1.f) fok = false;
        }
        for (int b = 0; b < B_; b++)
            g_flags[b] = iok ? pi[b] : (fok ? (pf[b] != 0.f ? 1 : 0) : (pc[b] ? 1 : 0));
    }
}

// ---------------- pack helpers ----------------
__device__ __forceinline__ uint32_t packbf(float a, float b) {
    __nv_bfloat162 p = __floats2bfloat162_rn(a, b);
    uint32_t u; memcpy(&u, &p, 4); return u;
}

// ---------------- weight fp32 -> bf16, 8 elems/thread (cols %8 == 0) -------------
__global__ void wcvt_kernel(const float* __restrict__ src, __nv_bfloat16* __restrict__ dst,
                            int src_rows, int cols) {
    size_t i8 = (size_t)blockIdx.x * blockDim.x + threadIdx.x;
    size_t total8 = (size_t)gridDim.y * src_rows * cols / 8;   // y merges nothing here
    size_t i = i8 * 8;
    if (i >= (size_t)src_rows * cols) return;
    float4 v0 = *(const float4*)&src[i];
    float4 v1 = *(const float4*)&src[i + 4];
    uint4 o;
    o.x = packbf(v0.x, v0.y); o.y = packbf(v0.z, v0.w);
    o.z = packbf(v1.x, v1.y); o.w = packbf(v1.z, v1.w);
    *(uint4*)&dst[i] = o;
}

// ---------------- w3 convert+pad (rows HID -> HIDP), both streams in one launch ----
__global__ void wcvt3_kernel(const float* __restrict__ srcp, const float* __restrict__ srcd,
                             __nv_bfloat16* __restrict__ dstp, __nv_bfloat16* __restrict__ dstd) {
    const float* src = blockIdx.y ? srcd : srcp;
    __nv_bfloat16* dst = blockIdx.y ? dstd : dstp;
    size_t i8 = (size_t)blockIdx.x * blockDim.x + threadIdx.x;
    size_t i = i8 * 8;
    if (i >= (size_t)HIDP * C_) return;
    int r = (int)(i / C_);
    uint4 o;
    if (r < HID) {
        float4 v0 = *(const float4*)&src[i];
        float4 v1 = *(const float4*)&src[i + 4];
        o.x = packbf(v0.x, v0.y); o.y = packbf(v0.z, v0.w);
        o.z = packbf(v1.x, v1.y); o.w = packbf(v1.z, v1.w);
    } else {
        o = make_uint4(0, 0, 0, 0);
    }
    *(uint4*)&dst[i] = o;
}

// ---------------- w12 permute+convert, 8 dst elems/thread, both streams ----------
// dst col 2j = src[:,j], 2j+1 = src[:,HID+j]
__global__ void wperm12_kernel(const float* __restrict__ srcp, const float* __restrict__ srcd,
                               __nv_bfloat16* __restrict__ dstp, __nv_bfloat16* __restrict__ dstd) {
    const float* src = blockIdx.y ? srcd : srcp;
    __nv_bfloat16* dst = blockIdx.y ? dstd : dstp;
    size_t i8 = (size_t)blockIdx.x * blockDim.x + threadIdx.x;
    size_t i = i8 * 8;
    if (i >= (size_t)C_ * N12I) return;
    int r = (int)(i / N12I), c0 = (int)(i - (size_t)r * N12I);
    int j0 = c0 >> 1;                       // 4 consecutive j, j0 % 4 == 0
    uint4 o;
    if (j0 + 3 < HID) {
        float4 x1 = *(const float4*)&src[(size_t)r * N12 + j0];          // aligned (j0%4==0)
        float2 x2a = *(const float2*)&src[(size_t)r * N12 + HID + j0];   // 8B aligned
        float2 x2b = *(const float2*)&src[(size_t)r * N12 + HID + j0 + 2];
        o.x = packbf(x1.x, x2a.x); o.y = packbf(x1.y, x2a.y);
        o.z = packbf(x1.z, x2b.x); o.w = packbf(x1.w, x2b.y);
    } else {
        float v[8];
#pragma unroll
        for (int t = 0; t < 4; t++) {
            int j = j0 + t;
            v[2 * t]     = (j < HID) ? src[(size_t)r * N12 + j] : 0.f;
            v[2 * t + 1] = (j < HID) ? src[(size_t)r * N12 + HID + j] : 0.f;
        }
        o.x = packbf(v[0], v[1]); o.y = packbf(v[2], v[3]);
        o.z = packbf(v[4], v[5]); o.w = packbf(v[6], v[7]);
    }
    *(uint4*)&dst[i] = o;
}

// ---------------- b12 permute ----------------
__global__ void bperm_kernel(const float* __restrict__ bp, const float* __restrict__ bd) {
    int j = blockIdx.x * blockDim.x + threadIdx.x;
    if (j >= N12I) return;
    int half = j & 1, jj = j >> 1;
    float vp = 0.f, vd = 0.f;
    if (jj < HID) {
        vp = bp[half ? HID + jj : jj];
        vd = bd[half ? HID + jj : jj];
    }
    g_scratch[OFF_B12P + j] = vp;
    g_scratch[OFF_B12D + j] = vd;
}

// ---------------- ada ----------------
__global__ void ada_kernel(const float* __restrict__ w_p, const float* __restrict__ b_p,
                           const float* __restrict__ w_d, const float* __restrict__ b_d) {
    int col = blockIdx.x * 128 + threadIdx.x;
    int st  = blockIdx.y;
    const float* w    = st ? w_d : w_p;
    const float* bias = st ? b_d : b_p;
    const float* sc = g_scratch + OFF_SILU;
    float a0 = 0, a1 = 0, a2 = 0, a3 = 0;
    for (int k = 0; k < C_; k++) {
        float wv = w[(size_t)k * 6144 + col];
        a0 += sc[k] * wv;
        a1 += sc[C_ + k] * wv;
        a2 += sc[2 * C_ + k] * wv;
        a3 += sc[3 * C_ + k] * wv;
    }
    float bv = bias[col];
    float* out = g_scratch + OFF_ADA + (size_t)st * 4 * 6144;
    out[0 * 6144 + col] = a0 + bv;
    out[1 * 6144 + col] = a1 + bv;
    out[2 * 6144 + col] = a2 + bv;
    out[3 * 6144 + col] = a3 + bv;
}

// ---------------- merged rms_norm + modulate (vectorized float4) ----------------
__global__ void norm_mod2_kernel(const float* __restrict__ xp, const float* __restrict__ xd,
                                 const float* __restrict__ gp, const float* __restrict__ gd,
                                 const float* __restrict__ ada, int sh_chunk, int sc_chunk,
                                 __nv_bfloat16* __restrict__ outp, __nv_bfloat16* __restrict__ outd,
                                 int bsp, int offp, int bsd, int offd) {
    int row = blockIdx.x;
    const float* x; const float* g; const float* adab; __nv_bfloat16* out;
    int Nseg, bstride, ooff;
    if (row < PTOK) {
        x = xp; g = gp; adab = ada; out = outp; Nseg = NP; bstride = bsp; ooff = offp;
    } else {
        row -= PTOK;
        x = xd; g = gd; adab = ada + 4 * 6144; out = outd; Nseg = ND; bstride = bsd; ooff = offd;
    }
    int b = row / Nseg, n = row - b * Nseg;
    const float* xr = x + (size_t)row * C_;
    __nv_bfloat16* orow = out + ((size_t)b * bstride + ooff + n) * C_;
    const float* ar = adab + (size_t)b * 6144;
    int tid = threadIdx.x;
    int cc0 = tid * 4;
    float4 xv = *(const float4*)&xr[cc0];
    float ss = xv.x * xv.x + xv.y * xv.y + xv.z * xv.z + xv.w * xv.w;
#pragma unroll
    for (int o = 16; o; o >>= 1) ss += __shfl_xor_sync(0xffffffffu, ss, o);
    __shared__ float red[8];
    if ((tid & 31) == 0) red[tid >> 5] = ss;
    __syncthreads();
    float tot = 0.f;
#pragma unroll
    for (int w = 0; w < 8; w++) tot += red[w];
    float r = rsqrtf(tot * (1.f / C_) + 1e-6f);
    float4 gv = *(const float4*)&g[cc0];
    float4 sc4 = *(const float4*)&ar[sc_chunk * C_ + cc0];
    float4 sh4 = *(const float4*)&ar[sh_chunk * C_ + cc0];
    float o0 = xv.x * r * gv.x * (1.f + sc4.x) + sh4.x;
    float o1 = xv.y * r * gv.y * (1.f + sc4.y) + sh4.y;
    float o2 = xv.z * r * gv.z * (1.f + sc4.z) + sh4.z;
    float o3 = xv.w * r * gv.w * (1.f + sc4.w) + sh4.w;
    *(uint2*)&orow[cc0] = make_uint2(packbf(o0, o1), packbf(o2, o3));
}

// ---------------- per-head rmsnorm + rope on bf16, q/k split by blockIdx.y ---------
__global__ void qknorm_rope_kernel(__nv_bfloat16* __restrict__ Q, __nv_bfloat16* __restrict__ Kp,
                                   const float* __restrict__ gq, const float* __restrict__ gk) {
    int sub = threadIdx.x >> 6;
    int idx = blockIdx.x * 4 + sub;
    int n = idx % NT;
    int d = threadIdx.x & 63;
    int pos = n < NP ? n : n - NP;
    __shared__ float sh[4][64];
    __shared__ float red[4][2];
    int i2 = d < 32 ? d : d - 32;
    float inv = expf(-logf(10000.f) * (2.f * i2) * (1.f / 64.f));
    float sv, cv;
    sincosf((float)pos * inv, &sv, &cv);
    int pass = blockIdx.y;
    __nv_bfloat16* ptr = (pass ? Kp : Q) + (size_t)idx * 64;
    const float* g = pass ? gk : gq;
    float x = __bfloat162float(ptr[d]);
    float ss = x * x;
#pragma unroll
    for (int o = 16; o; o >>= 1) ss += __shfl_xor_sync(0xffffffffu, ss, o);
    if ((d & 31) == 0) red[sub][d >> 5] = ss;
    __syncthreads();
    float tot = red[sub][0] + red[sub][1];
    float v = x * rsqrtf(tot * (1.f / 64.f) + 1e-6f) * g[d];
    sh[sub][d] = v;
    __syncthreads();
    float x1 = sh[sub][i2], x2 = sh[sub][i2 + 32];
    float rr = (d < 32) ? (x1 * cv - x2 * sv) : (x1 * sv + x2 * cv);
    if (pass == 0) rr *= 0.125f;
    ptr[d] = __float2bfloat16(rr);
}

// ---------------- epilogue params ----------------
struct EpiParams {
    int mode;                 // 1=qkv scatter(bf16), 2=proj residual, 3=final, 4=swiglu
    const float* bias;
    float* out;
    __nv_bfloat16* qbf; __nv_bfloat16* kbf; __nv_bfloat16* vbf;
    __nv_bfloat16* glout;
    const float* resid;
    const float* gate;
    int rpb;
    const float* xpix; const float* xdin; const float* ada;
    float* xap; float* xad;
};

__device__ __forceinline__ void epi_store(const EpiParams& ep, int N, int r, int cc, float v) {
    v += ep.bias[cc];
    if (ep.mode == 1) {
        int bb_ = r / NT, nn = r - bb_ * NT;
        int m = cc >> 10, rem = cc & 1023, h = rem >> 6, d = rem & 63;
        size_t dst = (((size_t)(bb_ * H_ + h) * NT) + nn) * DH + d;
        __nv_bfloat16* base = (m == 0) ? ep.qbf : (m == 1 ? ep.kbf : ep.vbf);
        base[dst] = __float2bfloat16(v);
    } else if (ep.mode == 2) {
        int bb_ = r / NT, nn = r - bb_ * NT;
        if (nn < NP) {
            size_t idx = (size_t)(bb_ * NP + nn) * C_ + cc;
            ep.xap[idx] = ep.xpix[idx] + ep.ada[bb_ * 6144 + 2 * C_ + cc] * v;
        } else {
            size_t idx = (size_t)(bb_ * ND + nn - NP) * C_ + cc;
            ep.xad[idx] = ep.xdin[idx] + ep.ada[4 * 6144 + bb_ * 6144 + 2 * C_ + cc] * v;
        }
    } else {
        int bb_ = r / ep.rpb;
        size_t idx = (size_t)r * N + cc;
        ep.out[idx] = ep.resid[idx] + ep.gate[bb_ * 6144 + cc] * v;
    }
}

// ---------------- asm helpers ----------------
__device__ __forceinline__ uint32_t s32(const void* p) {
    return (uint32_t)__cvta_generic_to_shared(p);
}
__device__ __forceinline__ void cp16(uint32_t dst, const void* src) {
    asm volatile("cp.async.cg.shared.global [%0], [%1], 16;" :: "r"(dst), "l"(src));
}
__device__ __forceinline__ void cp16p(uint32_t dst, const void* src, bool pred) {
    int sz = pred ? 16 : 0;
    asm volatile("cp.async.cg.shared.global [%0], [%1], 16, %2;" :: "r"(dst), "l"(src), "r"(sz));
}
__device__ __forceinline__ void cp_commit() { asm volatile("cp.async.commit_group;"); }
__device__ __forceinline__ void cp_wait1() { asm volatile("cp.async.wait_group 1;"); }

__device__ __forceinline__ void ldsm4(uint32_t* r, uint32_t a) {
    asm volatile("ldmatrix.sync.aligned.m8n8.x4.shared.b16 {%0,%1,%2,%3}, [%4];"
                 : "=r"(r[0]), "=r"(r[1]), "=r"(r[2]), "=r"(r[3]) : "r"(a));
}
__device__ __forceinline__ void ldsm4t(uint32_t* r, uint32_t a) {
    asm volatile("ldmatrix.sync.aligned.m8n8.x4.trans.shared.b16 {%0,%1,%2,%3}, [%4];"
                 : "=r"(r[0]), "=r"(r[1]), "=r"(r[2]), "=r"(r[3]) : "r"(a));
}
__device__ __forceinline__ void mma_bf16(float* d, const uint32_t* a, const uint32_t* b) {
    asm volatile(
        "mma.sync.aligned.m16n8k16.row.col.f32.bf16.bf16.f32 "
        "{%0,%1,%2,%3}, {%4,%5,%6,%7}, {%8,%9}, {%0,%1,%2,%3};"
        : "+f"(d[0]), "+f"(d[1]), "+f"(d[2]), "+f"(d[3])
        : "r"(a[0]), "r"(a[1]), "r"(a[2]), "r"(a[3]), "r"(b[0]), "r"(b[1]));
}

// ---------------- bf16 tensor-core GEMM, 128x128x32, 3-stage (R7-exact mainloop) ----
#define AROWB 80
#define BROWB 272
#define A_BYTES (128 * AROWB)
#define B_BYTES (32 * BROWB)
#define STAGE_B (A_BYTES + B_BYTES)
#define NSTAGE 3
#define GEMM_SMEM (NSTAGE * STAGE_B)

__global__ __launch_bounds__(256, 2) void bf16_gemm_kernel(
    const __nv_bfloat16* __restrict__ A, const __nv_bfloat16* __restrict__ A2, int blkM1,
    const __nv_bfloat16* __restrict__ Bw, const __nv_bfloat16* __restrict__ Bw2,
    int Nreal, int Npad, int Kpad, EpiParams ep, EpiParams ep2) {
    extern __shared__ char smem[];
    int tid = threadIdx.x;
    int warp = tid >> 5, lane = tid & 31;
    int wm = warp >> 2, wn = warp & 3;
    int g = lane >> 2, tig = lane & 3;
    bool seg2 = (int)blockIdx.y >= blkM1;
    const __nv_bfloat16* Ause = seg2 ? A2 : A;
    const __nv_bfloat16* Buse = seg2 ? Bw2 : Bw;
    int row0 = (seg2 ? blockIdx.y - blkM1 : blockIdx.y) * 128;
    int col0 = blockIdx.x * 128;
    int nkt = Kpad >> 5;

    float acc[4][4][4];
#pragma unroll
    for (int mi = 0; mi < 4; mi++)
#pragma unroll
        for (int ni = 0; ni < 4; ni++)
#pragma unroll
            for (int v = 0; v < 4; v++) acc[mi][ni][v] = 0.f;

    auto load_tile = [&](int stage, int kt) {
        int kb = kt * 32;
        char* As = smem + stage * STAGE_B;
        char* Bs = As + A_BYTES;
#pragma unroll
        for (int i = 0; i < 2; i++) {
            int cch = tid + i * 256;
            int row = cch >> 2, j = cch & 3;
            cp16(s32(As + row * AROWB + j * 16),
                 Ause + (size_t)(row0 + row) * Kpad + kb + j * 8);
        }
#pragma unroll
        for (int i = 0; i < 2; i++) {
            int cch = tid + i * 256;
            int kr = cch >> 4, j = cch & 15;
            int col = col0 + j * 8;
            cp16p(s32(Bs + kr * BROWB + j * 16),
                  Buse + (size_t)(kb + kr) * Npad + col, col < Npad);
        }
    };

    load_tile(0, 0); cp_commit();
    if (nkt > 1) load_tile(1, 1);
    cp_commit();

    int a_row = lane & 15, a_k8 = (lane >> 4) * 8;
    int b_k  = ((lane >> 3) & 1) * 8 + (lane & 7);
    int b_n8 = (lane >> 4) * 8;

    for (int kt = 0; kt < nkt; kt++) {
        cp_wait1();
        __syncthreads();
        if (kt + 2 < nkt) load_tile((kt + 2) % NSTAGE, kt + 2);
        cp_commit();
        const char* As = smem + (kt % NSTAGE) * STAGE_B;
        const char* Bs = As + A_BYTES;
#pragma unroll
        for (int ks = 0; ks < 2; ks++) {
            uint32_t a[4][4], b[2][4];
#pragma unroll
            for (int mi = 0; mi < 4; mi++)
                ldsm4(a[mi], s32(As + (wm * 64 + mi * 16 + a_row) * AROWB
                                    + (ks * 16 + a_k8) * 2));
#pragma unroll
            for (int nb = 0; nb < 2; nb++)
                ldsm4t(b[nb], s32(Bs + (ks * 16 + b_k) * BROWB
                                     + (wn * 32 + nb * 16 + b_n8) * 2));
#pragma unroll
            for (int mi = 0; mi < 4; mi++)
#pragma unroll
                for (int ni = 0; ni < 4; ni++)
                    mma_bf16(acc[mi][ni], a[mi], &b[ni >> 1][(ni & 1) * 2]);
        }
        __syncthreads();
    }

    const EpiParams& epu = seg2 ? ep2 : ep;
    if (epu.mode == 4) {
#pragma unroll
        for (int mi = 0; mi < 4; mi++) {
            int r1 = row0 + wm * 64 + mi * 16 + g;
            int r2 = r1 + 8;
#pragma unroll
            for (int ni = 0; ni < 4; ni++) {
                int cc0 = col0 + wn * 32 + ni * 8 + 2 * tig;
                float b0 = epu.bias[cc0], b1 = epu.bias[cc0 + 1];
                float x1a = acc[mi][ni][0] + b0, x2a = acc[mi][ni][1] + b1;
                float x1b = acc[mi][ni][2] + b0, x2b = acc[mi][ni][3] + b1;
                float ga = x1a / (1.f + expf(-x1a)) * x2a;
                float gb = x1b / (1.f + expf(-x1b)) * x2b;
                epu.glout[(size_t)r1 * HIDP + (cc0 >> 1)] = __float2bfloat16(ga);
                epu.glout[(size_t)r2 * HIDP + (cc0 >> 1)] = __float2bfloat16(gb);
            }
        }
        return;
    }

#pragma unroll
    for (int mi = 0; mi < 4; mi++) {
        int r1 = row0 + wm * 64 + mi * 16 + g;
        int r2 = r1 + 8;
#pragma unroll
        for (int ni = 0; ni < 4; ni++) {
            int cc0 = col0 + wn * 32 + ni * 8 + 2 * tig;
            if (cc0 < Nreal) {
                epi_store(epu, Nreal, r1, cc0, acc[mi][ni][0]);
                epi_store(epu, Nreal, r2, cc0, acc[mi][ni][2]);
            }
            if (cc0 + 1 < Nreal) {
                epi_store(epu, Nreal, r1, cc0 + 1, acc[mi][ni][1]);
                epi_store(epu, Nreal, r2, cc0 + 1, acc[mi][ni][3]);
            }
        }
    }
}

// ---------------- tensor-core flash attention: 128-row Q tiles, 256 threads ----------
#define KROW 144
#define ATILE (64 * KROW)
#define QTILE (128 * KROW)
#define ATTN_SMEM (QTILE + 3 * 2 * ATILE)   // 73728

__global__ __launch_bounds__(256, 2) void attn_mma_kernel(
    const __nv_bfloat16* __restrict__ Qb, const __nv_bfloat16* __restrict__ Kb,
    const __nv_bfloat16* __restrict__ Vb, __nv_bfloat16* __restrict__ O) {
    extern __shared__ char sma[];
    char* Qs = sma;
    int qi = blockIdx.x, bh = blockIdx.y;
    int b = bh >> 4, h = bh & 15;
    const __nv_bfloat16* Qg = Qb + (size_t)bh * NT * DH + (size_t)qi * 128 * DH;
    const __nv_bfloat16* Kg = Kb + (size_t)bh * NT * DH;
    const __nv_bfloat16* Vg = Vb + (size_t)bh * NT * DH;
    int tid = threadIdx.x, warp = tid >> 5, lane = tid & 31;
    int g = lane >> 2, tig = lane & 3;
    int ntile = (g_flags[b] && qi < 8) ? 16 : 20;

    auto load_kv = [&](int stage, int kt) {
        char* Ks = sma + QTILE + stage * 2 * ATILE;
        char* Vs = Ks + ATILE;
        const __nv_bfloat16* kg = Kg + (size_t)kt * 64 * DH;
        const __nv_bfloat16* vg = Vg + (size_t)kt * 64 * DH;
#pragma unroll
        for (int i = 0; i < 2; i++) {
            int cch = tid + i * 256;
            int row = cch >> 3, j = cch & 7;
            cp16(s32(Ks + row * KROW + j * 16), kg + row * DH + j * 8);
            cp16(s32(Vs + row * KROW + j * 16), vg + row * DH + j * 8);
        }
    };

#pragma unroll
    for (int i = 0; i < 4; i++) {
        int cch = tid + i * 256;
        int row = cch >> 3, j = cch & 7;
        cp16(s32(Qs + row * KROW + j * 16), Qg + row * DH + j * 8);
    }
    load_kv(0, 0); cp_commit();
    if (ntile > 1) load_kv(1, 1);
    cp_commit();

    uint32_t qf[4][4];
    float oacc[8][4];
#pragma unroll
    for (int j = 0; j < 8; j++)
#pragma unroll
        for (int v = 0; v < 4; v++) oacc[j][v] = 0.f;
    float m_g = -1e30f, m_g8 = -1e30f, l_g = 0.f, l_g8 = 0.f;

    int a_row = lane & 15, a_k8 = (lane >> 4) * 8;
    int b_k  = ((lane >> 3) & 1) * 8 + (lane & 7);
    int b_n8 = (lane >> 4) * 8;

    for (int kt = 0; kt < ntile; kt++) {
        cp_wait1();
        __syncthreads();
        if (kt + 2 < ntile) load_kv((kt + 2) % 3, kt + 2);
        cp_commit();
        const char* Ks = sma + QTILE + (kt % 3) * 2 * ATILE;
        const char* Vs = Ks + ATILE;

        if (kt == 0) {
#pragma unroll
            for (int ks = 0; ks < 4; ks++)
                ldsm4(qf[ks], s32(Qs + (warp * 16 + a_row) * KROW + (ks * 16 + a_k8) * 2));
        }

        float s[8][4];
#pragma unroll
        for (int j = 0; j < 8; j++)
#pragma unroll
            for (int v = 0; v < 4; v++) s[j][v] = 0.f;
#pragma unroll
        for (int ks = 0; ks < 4; ks++) {
#pragma unroll
            for (int jn2 = 0; jn2 < 4; jn2++) {
                uint32_t kf[4];
                ldsm4(kf, s32(Ks + (jn2 * 16 + a_row) * KROW + (ks * 16 + a_k8) * 2));
                uint32_t b0[2] = {kf[0], kf[2]};
                uint32_t b1[2] = {kf[1], kf[3]};
                mma_bf16(s[2 * jn2],     qf[ks], b0);
                mma_bf16(s[2 * jn2 + 1], qf[ks], b1);
            }
        }

        float mx0 = -1e30f, mx1 = -1e30f;
#pragma unroll
        for (int j = 0; j < 8; j++) {
            mx0 = fmaxf(mx0, fmaxf(s[j][0], s[j][1]));
            mx1 = fmaxf(mx1, fmaxf(s[j][2], s[j][3]));
        }
        mx0 = fmaxf(mx0, __shfl_xor_sync(0xffffffffu, mx0, 1));
        mx0 = fmaxf(mx0, __shfl_xor_sync(0xffffffffu, mx0, 2));
        mx1 = fmaxf(mx1, __shfl_xor_sync(0xffffffffu, mx1, 1));
        mx1 = fmaxf(mx1, __shfl_xor_sync(0xffffffffu, mx1, 2));
        float nm0 = fmaxf(m_g, mx0), nm1 = fmaxf(m_g8, mx1);
        float cr0 = __expf(m_g - nm0), cr1 = __expf(m_g8 - nm1);
        float ps0 = 0.f, ps1 = 0.f;
#pragma unroll
        for (int j = 0; j < 8; j++) {
            s[j][0] = __expf(s[j][0] - nm0);
            s[j][1] = __expf(s[j][1] - nm0);
            s[j][2] = __expf(s[j][2] - nm1);
            s[j][3] = __expf(s[j][3] - nm1);
            ps0 += s[j][0] + s[j][1];
            ps1 += s[j][2] + s[j][3];
        }
        ps0 += __shfl_xor_sync(0xffffffffu, ps0, 1);
        ps0 += __shfl_xor_sync(0xffffffffu, ps0, 2);
        ps1 += __shfl_xor_sync(0xffffffffu, ps1, 1);
        ps1 += __shfl_xor_sync(0xffffffffu, ps1, 2);
        l_g = l_g * cr0 + ps0;
        l_g8 = l_g8 * cr1 + ps1;
        m_g = nm0; m_g8 = nm1;
#pragma unroll
        for (int j = 0; j < 8; j++) {
            oacc[j][0] *= cr0; oacc[j][1] *= cr0;
            oacc[j][2] *= cr1; oacc[j][3] *= cr1;
        }

#pragma unroll
        for (int ki = 0; ki < 4; ki++) {
            uint32_t pa[4];
            __nv_bfloat162 t0 = __floats2bfloat162_rn(s[2 * ki][0], s[2 * ki][1]);
            __nv_bfloat162 t1 = __floats2bfloat162_rn(s[2 * ki][2], s[2 * ki][3]);
            __nv_bfloat162 t2 = __floats2bfloat162_rn(s[2 * ki + 1][0], s[2 * ki + 1][1]);
            __nv_bfloat162 t3 = __floats2bfloat162_rn(s[2 * ki + 1][2], s[2 * ki + 1][3]);
            memcpy(&pa[0], &t0, 4); memcpy(&pa[1], &t1, 4);
            memcpy(&pa[2], &t2, 4); memcpy(&pa[3], &t3, 4);
#pragma unroll
            for (int jn = 0; jn < 4; jn++) {
                uint32_t vf[4];
                ldsm4t(vf, s32(Vs + (ki * 16 + b_k) * KROW + (jn * 16 + b_n8) * 2));
                mma_bf16(oacc[2 * jn],     pa, &vf[0]);
                mma_bf16(oacc[2 * jn + 1], pa, &vf[2]);
            }
        }
        __syncthreads();
    }

    float inv0 = 1.f / l_g, inv1 = 1.f / l_g8;
    int t1 = b * NT + qi * 128 + warp * 16 + g;
    __nv_bfloat16* o1 = O + (size_t)t1 * C_ + h * DH;
    __nv_bfloat16* o2 = o1 + 8 * C_;
#pragma unroll
    for (int j = 0; j < 8; j++) {
        __nv_bfloat162 w0 = __floats2bfloat162_rn(oacc[j][0] * inv0, oacc[j][1] * inv0);
        __nv_bfloat162 w1 = __floats2bfloat162_rn(oacc[j][2] * inv1, oacc[j][3] * inv1);
        *(__nv_bfloat162*)&o1[j * 8 + 2 * tig] = w0;
        *(__nv_bfloat162*)&o2[j * 8 + 2 * tig] = w1;
    }
}

// ---------------- launch ----------------
extern "C" void kernel_launch(void* const* d_in, const int* in_sizes, int n_in,
                              void* d_out, int out_size) {
    const float* x_pixel = (const float*)d_in[0];
    const float* x_dino  = (const float*)d_in[1];
    const float* c       = (const float*)d_in[2];
    const float* w_ada_p = (const float*)d_in[3];
    const float* b_ada_p = (const float*)d_in[4];
    const float* w_ada_d = (const float*)d_in[5];
    const float* b_ada_d = (const float*)d_in[6];
    const float* g_n1p   = (const float*)d_in[7];
    const float* g_n1d   = (const float*)d_in[8];
    const float* g_n2p   = (const float*)d_in[9];
    const float* g_n2d   = (const float*)d_in[10];
    const float* w_qkv   = (const float*)d_in[11];
    const float* b_qkv   = (const float*)d_in[12];
    const float* g_qn    = (const float*)d_in[13];
    const float* g_kn    = (const float*)d_in[14];
    const float* w_proj  = (const float*)d_in[15];
    const float* b_proj  = (const float*)d_in[16];
    const float* w12_p   = (const float*)d_in[17];
    const float* b12_p   = (const float*)d_in[18];
    const float* w3_p    = (const float*)d_in[19];
    const float* b3_p    = (const float*)d_in[20];
    const float* w12_d   = (const float*)d_in[21];
    const float* b12_d   = (const float*)d_in[22];
    const float* w3_d    = (const float*)d_in[23];
    const float* b3_d    = (const float*)d_in[24];
    const void*  flags   = d_in[25];
    float* out = (float*)d_out;

    float* S = nullptr;
    cudaGetSymbolAddress((void**)&S, g_scratch);
    __nv_bfloat16* BF = nullptr;
    cudaGetSymbolAddress((void**)&BF, g_bf);

    float* ada  = S + OFF_ADA;
    float* xap  = S + OFF_XAP;
    float* xad  = S + OFF_XAD;

    __nv_bfloat16* xcb   = BF + BO_XC;
    __nv_bfloat16* attnb = BF + BO_ATTN;
    __nv_bfloat16* h2pb  = BF + BO_H2P;
    __nv_bfloat16* h2db  = BF + BO_H2D;
    __nv_bfloat16* glpb  = BF + BO_GLP;
    __nv_bfloat16* gldb  = BF + BO_GLD;
    __nv_bfloat16* qb    = BF + BO_QB;
    __nv_bfloat16* kb    = BF + BO_KB;
    __nv_bfloat16* vb    = BF + BO_VB;
    __nv_bfloat16* wqkvb = BF + BO_WQKV;
    __nv_bfloat16* wprjb = BF + BO_WPROJ;
    __nv_bfloat16* w12pb = BF + BO_W12P;
    __nv_bfloat16* w12db = BF + BO_W12D;
    __nv_bfloat16* w3pb  = BF + BO_W3P;
    __nv_bfloat16* w3db  = BF + BO_W3D;

    cudaFuncSetAttribute(bf16_gemm_kernel, cudaFuncAttributeMaxDynamicSharedMemorySize, GEMM_SMEM);
    cudaFuncSetAttribute(attn_mma_kernel, cudaFuncAttributeMaxDynamicSharedMemorySize, ATTN_SMEM);

    wcvt_kernel<<<(int)(((size_t)C_ * 3 * C_ / 8 + 255) / 256), 256>>>(w_qkv, wqkvb, C_, 3 * C_);
    wcvt_kernel<<<(int)(((size_t)C_ * C_ / 8 + 255) / 256), 256>>>(w_proj, wprjb, C_, C_);
    wperm12_kernel<<<dim3((int)(((size_t)C_ * N12I / 8 + 255) / 256), 2), 256>>>(w12_p, w12_d, w12pb, w12db);
    wcvt3_kernel<<<dim3((int)(((size_t)HIDP * C_ / 8 + 255) / 256), 2), 256>>>(w3_p, w3_d, w3pb, w3db);
    bperm_kernel<<<(N12I + 255) / 256, 256>>>(b12_p, b12_d);

    prep_kernel<<<16, 256>>>(c, flags);
    ada_kernel<<<dim3(48, 2), 128>>>(w_ada_p, b_ada_p, w_ada_d, b_ada_d);

    norm_mod2_kernel<<<TOK, 256>>>(x_pixel, x_dino, g_n1p, g_n1d, ada, 0, 1,
                                   xcb, xcb, NT, 0, NT, NP);

    EpiParams e1 = {}; e1.mode = 1; e1.bias = b_qkv; e1.qbf = qb; e1.kbf = kb; e1.vbf = vb;
    bf16_gemm_kernel<<<dim3(24, 40), 256, GEMM_SMEM>>>(xcb, xcb, 1 << 30, wqkvb, wqkvb,
                                                       3 * C_, 3 * C_, C_, e1, e1);

    qknorm_rope_kernel<<<dim3(B_ * H_ * NT / 4, 2), 256>>>(qb, kb, g_qn, g_kn);

    attn_mma_kernel<<<dim3(10, 64), 256, ATTN_SMEM>>>(qb, kb, vb, attnb);

    EpiParams e2 = {}; e2.mode = 2; e2.bias = b_proj; e2.xpix = x_pixel; e2.xdin = x_dino;
    e2.ada = ada; e2.xap = xap; e2.xad = xad;
    bf16_gemm_kernel<<<dim3(8, 40), 256, GEMM_SMEM>>>(attnb, attnb, 1 << 30, wprjb, wprjb,
                                                      C_, C_, C_, e2, e2);

    norm_mod2_kernel<<<TOK, 256>>>(xap, xad, g_n2p, g_n2d, ada, 3, 4,
                                   h2pb, h2db, NP, 0, ND, 0);

    EpiParams e3 = {}; e3.mode = 4; e3.bias = S + OFF_B12P; e3.glout = glpb;
    EpiParams e4 = {}; e4.mode = 4; e4.bias = S + OFF_B12D; e4.glout = gldb;
    bf16_gemm_kernel<<<dim3(43, 40), 256, GEMM_SMEM>>>(h2pb, h2db, 32, w12pb, w12db,
                                                       N12I, N12I, C_, e3, e4);

    EpiParams e5 = {}; e5.mode = 3; e5.bias = b3_p; e5.resid = xap;
    e5.gate = ada + 5 * C_; e5.rpb = NP; e5.out = out;
    EpiParams e6 = {}; e6.mode = 3; e6.bias = b3_d; e6.resid = xad;
    e6.gate = ada + 4 * 6144 + 5 * C_; e6.rpb = ND; e6.out = out + (size_t)PTOK * C_;
    bf16_gemm_kernel<<<dim3(8, 40), 256, GEMM_SMEM>>>(glpb, gldb, 32, w3pb, w3db,
                                                      C_, C_, HIDP, e5, e6);
}

// round 14
// speedup vs baseline: 1.0059x; 1.0059x over previous
#include <cuda_runtime.h>
#include <cuda_bf16.h>
#include <math.h>
#include <stdint.h>

#define B_  4
#define NP  1024
#define ND  256
#define NT  1280
#define C_  1024
#define H_  16
#define DH  64
#define HID 2730
#define HIDP 2752
#define N12  (2*HID)       // 5460
#define N12I (2*HIDP)      // 5504 (43*128)
#define TOK  (B_*NT)   // 5120
#define PTOK (B_*NP)   // 4096
#define DTOK (B_*ND)   // 1024

// ---------------- fp32 scratch ----------------
constexpr size_t OFF_SILU = 0;
constexpr size_t OFF_ADA  = OFF_SILU + 4096;
constexpr size_t OFF_XAP  = OFF_ADA  + 49152;
constexpr size_t OFF_XAD  = OFF_XAP  + (size_t)PTOK*C_;
constexpr size_t OFF_B12P = OFF_XAD  + (size_t)DTOK*C_;
constexpr size_t OFF_B12D = OFF_B12P + N12I;
constexpr size_t OFF_END  = OFF_B12D + N12I;

__device__ __align__(16) float g_scratch[OFF_END];
__device__ int g_flags[B_];

// ---------------- bf16 scratch ----------------
constexpr size_t BO_XC    = 0;
constexpr size_t BO_ATTN  = BO_XC    + (size_t)TOK*C_;
constexpr size_t BO_H2P   = BO_ATTN  + (size_t)TOK*C_;
constexpr size_t BO_H2D   = BO_H2P   + (size_t)PTOK*C_;
constexpr size_t BO_GLP   = BO_H2D   + (size_t)DTOK*C_;
constexpr size_t BO_GLD   = BO_GLP   + (size_t)PTOK*HIDP;
constexpr size_t BO_QB    = BO_GLD   + (size_t)DTOK*HIDP;
constexpr size_t BO_KB    = BO_QB    + (size_t)TOK*C_;
constexpr size_t BO_VB    = BO_KB    + (size_t)TOK*C_;
constexpr size_t BO_WQKV  = BO_VB    + (size_t)TOK*C_;
constexpr size_t BO_WPROJ = BO_WQKV  + (size_t)C_*3*C_;
constexpr size_t BO_W12P  = BO_WPROJ + (size_t)C_*C_;
constexpr size_t BO_W12D  = BO_W12P  + (size_t)C_*N12I;
constexpr size_t BO_W3P   = BO_W12D  + (size_t)C_*N12I;
constexpr size_t BO_W3D   = BO_W3P   + (size_t)HIDP*C_;
constexpr size_t BO_END   = BO_W3D   + (size_t)HIDP*C_;

__device__ __align__(16) __nv_bfloat16 g_bf[BO_END];

// ---------------- prep ----------------
__global__ void prep_kernel(const float* __restrict__ c, const void* __restrict__ flags) {
    int i = blockIdx.x * blockDim.x + threadIdx.x;
    if (i < B_ * C_) {
        float v = c[i];
        g_scratch[OFF_SILU + i] = v / (1.f + expf(-v));
    }
    if (blockIdx.x == 0 && threadIdx.x == 0) {
        const int* pi = (const int*)flags;
        const float* pf = (const float*)flags;
        const unsigned char* pc = (const unsigned char*)flags;
        bool iok = true, fok = true;
        for (int b = 0; b < B_; b++) {
            int t = pi[b]; if (t != 0 && t != 1) iok = false;
            float f = pf[b]; if (f != 0.f && f != 1.f) fok = false;
        }
        for (int b = 0; b < B_; b++)
            g_flags[b] = iok ? pi[b] : (fok ? (pf[b] != 0.f ? 1 : 0) : (pc[b] ? 1 : 0));
    }
}

// ---------------- pack helpers ----------------
__device__ __forceinline__ uint32_t packbf(float a, float b) {
    __nv_bfloat162 p = __floats2bfloat162_rn(a, b);
    uint32_t u; memcpy(&u, &p, 4); return u;
}

// ---------------- weight fp32 -> bf16, 8 elems/thread ----------------
__global__ void wcvt_kernel(const float* __restrict__ src, __nv_bfloat16* __restrict__ dst,
                            int src_rows, int cols) {
    size_t i8 = (size_t)blockIdx.x * blockDim.x + threadIdx.x;
    size_t i = i8 * 8;
    if (i >= (size_t)src_rows * cols) return;
    float4 v0 = *(const float4*)&src[i];
    float4 v1 = *(const float4*)&src[i + 4];
    uint4 o;
    o.x = packbf(v0.x, v0.y); o.y = packbf(v0.z, v0.w);
    o.z = packbf(v1.x, v1.y); o.w = packbf(v1.z, v1.w);
    *(uint4*)&dst[i] = o;
}

// ---------------- w3 convert+pad, both streams in one launch ----------------
__global__ void wcvt3_kernel(const float* __restrict__ srcp, const float* __restrict__ srcd,
                             __nv_bfloat16* __restrict__ dstp, __nv_bfloat16* __restrict__ dstd) {
    const float* src = blockIdx.y ? srcd : srcp;
    __nv_bfloat16* dst = blockIdx.y ? dstd : dstp;
    size_t i8 = (size_t)blockIdx.x * blockDim.x + threadIdx.x;
    size_t i = i8 * 8;
    if (i >= (size_t)HIDP * C_) return;
    int r = (int)(i / C_);
    uint4 o;
    if (r < HID) {
        float4 v0 = *(const float4*)&src[i];
        float4 v1 = *(const float4*)&src[i + 4];
        o.x = packbf(v0.x, v0.y); o.y = packbf(v0.z, v0.w);
        o.z = packbf(v1.x, v1.y); o.w = packbf(v1.z, v1.w);
    } else {
        o = make_uint4(0, 0, 0, 0);
    }
    *(uint4*)&dst[i] = o;
}

// ---------------- w12 permute+convert, both streams ----------------
__global__ void wperm12_kernel(const float* __restrict__ srcp, const float* __restrict__ srcd,
                               __nv_bfloat16* __restrict__ dstp, __nv_bfloat16* __restrict__ dstd) {
    const float* src = blockIdx.y ? srcd : srcp;
    __nv_bfloat16* dst = blockIdx.y ? dstd : dstp;
    size_t i8 = (size_t)blockIdx.x * blockDim.x + threadIdx.x;
    size_t i = i8 * 8;
    if (i >= (size_t)C_ * N12I) return;
    int r = (int)(i / N12I), c0 = (int)(i - (size_t)r * N12I);
    int j0 = c0 >> 1;
    uint4 o;
    if (j0 + 3 < HID) {
        float4 x1 = *(const float4*)&src[(size_t)r * N12 + j0];
        float2 x2a = *(const float2*)&src[(size_t)r * N12 + HID + j0];
        float2 x2b = *(const float2*)&src[(size_t)r * N12 + HID + j0 + 2];
        o.x = packbf(x1.x, x2a.x); o.y = packbf(x1.y, x2a.y);
        o.z = packbf(x1.z, x2b.x); o.w = packbf(x1.w, x2b.y);
    } else {
        float v[8];
#pragma unroll
        for (int t = 0; t < 4; t++) {
            int j = j0 + t;
            v[2 * t]     = (j < HID) ? src[(size_t)r * N12 + j] : 0.f;
            v[2 * t + 1] = (j < HID) ? src[(size_t)r * N12 + HID + j] : 0.f;
        }
        o.x = packbf(v[0], v[1]); o.y = packbf(v[2], v[3]);
        o.z = packbf(v[4], v[5]); o.w = packbf(v[6], v[7]);
    }
    *(uint4*)&dst[i] = o;
}

// ---------------- b12 permute ----------------
__global__ void bperm_kernel(const float* __restrict__ bp, const float* __restrict__ bd) {
    int j = blockIdx.x * blockDim.x + threadIdx.x;
    if (j >= N12I) return;
    int half = j & 1, jj = j >> 1;
    float vp = 0.f, vd = 0.f;
    if (jj < HID) {
        vp = bp[half ? HID + jj : jj];
        vd = bd[half ? HID + jj : jj];
    }
    g_scratch[OFF_B12P + j] = vp;
    g_scratch[OFF_B12D + j] = vd;
}

// ---------------- ada ----------------
__global__ void ada_kernel(const float* __restrict__ w_p, const float* __restrict__ b_p,
                           const float* __restrict__ w_d, const float* __restrict__ b_d) {
    int col = blockIdx.x * 128 + threadIdx.x;
    int st  = blockIdx.y;
    const float* w    = st ? w_d : w_p;
    const float* bias = st ? b_d : b_p;
    const float* sc = g_scratch + OFF_SILU;
    float a0 = 0, a1 = 0, a2 = 0, a3 = 0;
    for (int k = 0; k < C_; k++) {
        float wv = w[(size_t)k * 6144 + col];
        a0 += sc[k] * wv;
        a1 += sc[C_ + k] * wv;
        a2 += sc[2 * C_ + k] * wv;
        a3 += sc[3 * C_ + k] * wv;
    }
    float bv = bias[col];
    float* out = g_scratch + OFF_ADA + (size_t)st * 4 * 6144;
    out[0 * 6144 + col] = a0 + bv;
    out[1 * 6144 + col] = a1 + bv;
    out[2 * 6144 + col] = a2 + bv;
    out[3 * 6144 + col] = a3 + bv;
}

// ---------------- merged rms_norm + modulate (vectorized float4) ----------------
__global__ void norm_mod2_kernel(const float* __restrict__ xp, const float* __restrict__ xd,
                                 const float* __restrict__ gp, const float* __restrict__ gd,
                                 const float* __restrict__ ada, int sh_chunk, int sc_chunk,
                                 __nv_bfloat16* __restrict__ outp, __nv_bfloat16* __restrict__ outd,
                                 int bsp, int offp, int bsd, int offd) {
    int row = blockIdx.x;
    const float* x; const float* g; const float* adab; __nv_bfloat16* out;
    int Nseg, bstride, ooff;
    if (row < PTOK) {
        x = xp; g = gp; adab = ada; out = outp; Nseg = NP; bstride = bsp; ooff = offp;
    } else {
        row -= PTOK;
        x = xd; g = gd; adab = ada + 4 * 6144; out = outd; Nseg = ND; bstride = bsd; ooff = offd;
    }
    int b = row / Nseg, n = row - b * Nseg;
    const float* xr = x + (size_t)row * C_;
    __nv_bfloat16* orow = out + ((size_t)b * bstride + ooff + n) * C_;
    const float* ar = adab + (size_t)b * 6144;
    int tid = threadIdx.x;
    int cc0 = tid * 4;
    float4 xv = *(const float4*)&xr[cc0];
    float ss = xv.x * xv.x + xv.y * xv.y + xv.z * xv.z + xv.w * xv.w;
#pragma unroll
    for (int o = 16; o; o >>= 1) ss += __shfl_xor_sync(0xffffffffu, ss, o);
    __shared__ float red[8];
    if ((tid & 31) == 0) red[tid >> 5] = ss;
    __syncthreads();
    float tot = 0.f;
#pragma unroll
    for (int w = 0; w < 8; w++) tot += red[w];
    float r = rsqrtf(tot * (1.f / C_) + 1e-6f);
    float4 gv = *(const float4*)&g[cc0];
    float4 sc4 = *(const float4*)&ar[sc_chunk * C_ + cc0];
    float4 sh4 = *(const float4*)&ar[sh_chunk * C_ + cc0];
    float o0 = xv.x * r * gv.x * (1.f + sc4.x) + sh4.x;
    float o1 = xv.y * r * gv.y * (1.f + sc4.y) + sh4.y;
    float o2 = xv.z * r * gv.z * (1.f + sc4.z) + sh4.z;
    float o3 = xv.w * r * gv.w * (1.f + sc4.w) + sh4.w;
    *(uint2*)&orow[cc0] = make_uint2(packbf(o0, o1), packbf(o2, o3));
}

// ---------------- per-head rmsnorm + rope on bf16, q/k split by blockIdx.y ---------
__global__ void qknorm_rope_kernel(__nv_bfloat16* __restrict__ Q, __nv_bfloat16* __restrict__ Kp,
                                   const float* __restrict__ gq, const float* __restrict__ gk) {
    int sub = threadIdx.x >> 6;
    int idx = blockIdx.x * 4 + sub;
    int n = idx % NT;
    int d = threadIdx.x & 63;
    int pos = n < NP ? n : n - NP;
    __shared__ float sh[4][64];
    __shared__ float red[4][2];
    int i2 = d < 32 ? d : d - 32;
    float inv = expf(-logf(10000.f) * (2.f * i2) * (1.f / 64.f));
    float sv, cv;
    sincosf((float)pos * inv, &sv, &cv);
    int pass = blockIdx.y;
    __nv_bfloat16* ptr = (pass ? Kp : Q) + (size_t)idx * 64;
    const float* g = pass ? gk : gq;
    float x = __bfloat162float(ptr[d]);
    float ss = x * x;
#pragma unroll
    for (int o = 16; o; o >>= 1) ss += __shfl_xor_sync(0xffffffffu, ss, o);
    if ((d & 31) == 0) red[sub][d >> 5] = ss;
    __syncthreads();
    float tot = red[sub][0] + red[sub][1];
    float v = x * rsqrtf(tot * (1.f / 64.f) + 1e-6f) * g[d];
    sh[sub][d] = v;
    __syncthreads();
    float x1 = sh[sub][i2], x2 = sh[sub][i2 + 32];
    float rr = (d < 32) ? (x1 * cv - x2 * sv) : (x1 * sv + x2 * cv);
    if (pass == 0) rr *= 0.125f;
    ptr[d] = __float2bfloat16(rr);
}

// ---------------- epilogue params ----------------
struct EpiParams {
    int mode;                 // 1=qkv scatter(bf16), 2=proj residual, 3=final, 4=swiglu
    const float* bias;
    float* out;
    __nv_bfloat16* qbf; __nv_bfloat16* kbf; __nv_bfloat16* vbf;
    __nv_bfloat16* glout;
    const float* resid;
    const float* gate;
    int rpb;
    const float* xpix; const float* xdin; const float* ada;
    float* xap; float* xad;
};

__device__ __forceinline__ void epi_store(const EpiParams& ep, int N, int r, int cc, float v) {
    v += ep.bias[cc];
    if (ep.mode == 1) {
        int bb_ = r / NT, nn = r - bb_ * NT;
        int m = cc >> 10, rem = cc & 1023, h = rem >> 6, d = rem & 63;
        size_t dst = (((size_t)(bb_ * H_ + h) * NT) + nn) * DH + d;
        __nv_bfloat16* base = (m == 0) ? ep.qbf : (m == 1 ? ep.kbf : ep.vbf);
        base[dst] = __float2bfloat16(v);
    } else if (ep.mode == 2) {
        int bb_ = r / NT, nn = r - bb_ * NT;
        if (nn < NP) {
            size_t idx = (size_t)(bb_ * NP + nn) * C_ + cc;
            ep.xap[idx] = ep.xpix[idx] + ep.ada[bb_ * 6144 + 2 * C_ + cc] * v;
        } else {
            size_t idx = (size_t)(bb_ * ND + nn - NP) * C_ + cc;
            ep.xad[idx] = ep.xdin[idx] + ep.ada[4 * 6144 + bb_ * 6144 + 2 * C_ + cc] * v;
        }
    } else {
        int bb_ = r / ep.rpb;
        size_t idx = (size_t)r * N + cc;
        ep.out[idx] = ep.resid[idx] + ep.gate[bb_ * 6144 + cc] * v;
    }
}

// ---------------- asm helpers ----------------
__device__ __forceinline__ uint32_t s32(const void* p) {
    return (uint32_t)__cvta_generic_to_shared(p);
}
__device__ __forceinline__ void cp16(uint32_t dst, const void* src) {
    asm volatile("cp.async.cg.shared.global [%0], [%1], 16;" :: "r"(dst), "l"(src));
}
__device__ __forceinline__ void cp16p(uint32_t dst, const void* src, bool pred) {
    int sz = pred ? 16 : 0;
    asm volatile("cp.async.cg.shared.global [%0], [%1], 16, %2;" :: "r"(dst), "l"(src), "r"(sz));
}
__device__ __forceinline__ void cp_commit() { asm volatile("cp.async.commit_group;"); }
__device__ __forceinline__ void cp_wait1() { asm volatile("cp.async.wait_group 1;"); }

__device__ __forceinline__ void ldsm4(uint32_t* r, uint32_t a) {
    asm volatile("ldmatrix.sync.aligned.m8n8.x4.shared.b16 {%0,%1,%2,%3}, [%4];"
                 : "=r"(r[0]), "=r"(r[1]), "=r"(r[2]), "=r"(r[3]) : "r"(a));
}
__device__ __forceinline__ void ldsm4t(uint32_t* r, uint32_t a) {
    asm volatile("ldmatrix.sync.aligned.m8n8.x4.trans.shared.b16 {%0,%1,%2,%3}, [%4];"
                 : "=r"(r[0]), "=r"(r[1]), "=r"(r[2]), "=r"(r[3]) : "r"(a));
}
__device__ __forceinline__ void mma_bf16(float* d, const uint32_t* a, const uint32_t* b) {
    asm volatile(
        "mma.sync.aligned.m16n8k16.row.col.f32.bf16.bf16.f32 "
        "{%0,%1,%2,%3}, {%4,%5,%6,%7}, {%8,%9}, {%0,%1,%2,%3};"
        : "+f"(d[0]), "+f"(d[1]), "+f"(d[2]), "+f"(d[3])
        : "r"(a[0]), "r"(a[1]), "r"(a[2]), "r"(a[3]), "r"(b[0]), "r"(b[1]));
}

// ---------------- bf16 tensor-core GEMM, 128x128x32, 3-stage ----------------
#define AROWB 80
#define BROWB 272
#define A_BYTES (128 * AROWB)
#define B_BYTES (32 * BROWB)
#define STAGE_B (A_BYTES + B_BYTES)
#define NSTAGE 3
#define GEMM_SMEM (NSTAGE * STAGE_B)

__global__ __launch_bounds__(256, 2) void bf16_gemm_kernel(
    const __nv_bfloat16* __restrict__ A, const __nv_bfloat16* __restrict__ A2, int blkM1,
    const __nv_bfloat16* __restrict__ Bw, const __nv_bfloat16* __restrict__ Bw2,
    int Nreal, int Npad, int Kpad, EpiParams ep, EpiParams ep2) {
    extern __shared__ char smem[];
    int tid = threadIdx.x;
    int warp = tid >> 5, lane = tid & 31;
    int wm = warp >> 2, wn = warp & 3;
    int g = lane >> 2, tig = lane & 3;
    bool seg2 = (int)blockIdx.y >= blkM1;
    const __nv_bfloat16* Ause = seg2 ? A2 : A;
    const __nv_bfloat16* Buse = seg2 ? Bw2 : Bw;
    int row0 = (seg2 ? blockIdx.y - blkM1 : blockIdx.y) * 128;
    int col0 = blockIdx.x * 128;
    int nkt = Kpad >> 5;

    float acc[4][4][4];
#pragma unroll
    for (int mi = 0; mi < 4; mi++)
#pragma unroll
        for (int ni = 0; ni < 4; ni++)
#pragma unroll
            for (int v = 0; v < 4; v++) acc[mi][ni][v] = 0.f;

    auto load_tile = [&](int stage, int kt) {
        int kb = kt * 32;
        char* As = smem + stage * STAGE_B;
        char* Bs = As + A_BYTES;
#pragma unroll
        for (int i = 0; i < 2; i++) {
            int cch = tid + i * 256;
            int row = cch >> 2, j = cch & 3;
            cp16(s32(As + row * AROWB + j * 16),
                 Ause + (size_t)(row0 + row) * Kpad + kb + j * 8);
        }
#pragma unroll
        for (int i = 0; i < 2; i++) {
            int cch = tid + i * 256;
            int kr = cch >> 4, j = cch & 15;
            int col = col0 + j * 8;
            cp16p(s32(Bs + kr * BROWB + j * 16),
                  Buse + (size_t)(kb + kr) * Npad + col, col < Npad);
        }
    };

    load_tile(0, 0); cp_commit();
    if (nkt > 1) load_tile(1, 1);
    cp_commit();

    int a_row = lane & 15, a_k8 = (lane >> 4) * 8;
    int b_k  = ((lane >> 3) & 1) * 8 + (lane & 7);
    int b_n8 = (lane >> 4) * 8;

    for (int kt = 0; kt < nkt; kt++) {
        cp_wait1();
        __syncthreads();
        if (kt + 2 < nkt) load_tile((kt + 2) % NSTAGE, kt + 2);
        cp_commit();
        const char* As = smem + (kt % NSTAGE) * STAGE_B;
        const char* Bs = As + A_BYTES;
#pragma unroll
        for (int ks = 0; ks < 2; ks++) {
            uint32_t a[4][4], b[2][4];
#pragma unroll
            for (int mi = 0; mi < 4; mi++)
                ldsm4(a[mi], s32(As + (wm * 64 + mi * 16 + a_row) * AROWB
                                    + (ks * 16 + a_k8) * 2));
#pragma unroll
            for (int nb = 0; nb < 2; nb++)
                ldsm4t(b[nb], s32(Bs + (ks * 16 + b_k) * BROWB
                                     + (wn * 32 + nb * 16 + b_n8) * 2));
#pragma unroll
            for (int mi = 0; mi < 4; mi++)
#pragma unroll
                for (int ni = 0; ni < 4; ni++)
                    mma_bf16(acc[mi][ni], a[mi], &b[ni >> 1][(ni & 1) * 2]);
        }
        __syncthreads();
    }

    const EpiParams& epu = seg2 ? ep2 : ep;
    if (epu.mode == 4) {
#pragma unroll
        for (int mi = 0; mi < 4; mi++) {
            int r1 = row0 + wm * 64 + mi * 16 + g;
            int r2 = r1 + 8;
#pragma unroll
            for (int ni = 0; ni < 4; ni++) {
                int cc0 = col0 + wn * 32 + ni * 8 + 2 * tig;
                float b0 = epu.bias[cc0], b1 = epu.bias[cc0 + 1];
                float x1a = acc[mi][ni][0] + b0, x2a = acc[mi][ni][1] + b1;
                float x1b = acc[mi][ni][2] + b0, x2b = acc[mi][ni][3] + b1;
                float ga = x1a / (1.f + expf(-x1a)) * x2a;
                float gb = x1b / (1.f + expf(-x1b)) * x2b;
                epu.glout[(size_t)r1 * HIDP + (cc0 >> 1)] = __float2bfloat16(ga);
                epu.glout[(size_t)r2 * HIDP + (cc0 >> 1)] = __float2bfloat16(gb);
            }
        }
        return;
    }

#pragma unroll
    for (int mi = 0; mi < 4; mi++) {
        int r1 = row0 + wm * 64 + mi * 16 + g;
        int r2 = r1 + 8;
#pragma unroll
        for (int ni = 0; ni < 4; ni++) {
            int cc0 = col0 + wn * 32 + ni * 8 + 2 * tig;
            if (cc0 < Nreal) {
                epi_store(epu, Nreal, r1, cc0, acc[mi][ni][0]);
                epi_store(epu, Nreal, r2, cc0, acc[mi][ni][2]);
            }
            if (cc0 + 1 < Nreal) {
                epi_store(epu, Nreal, r1, cc0 + 1, acc[mi][ni][1]);
                epi_store(epu, Nreal, r2, cc0 + 1, acc[mi][ni][3]);
            }
        }
    }
}

// ---------------- tensor-core flash attention: 128-row Q tiles, 256 threads ----------
#define KROW 144
#define ATILE (64 * KROW)
#define QTILE (128 * KROW)
#define ATTN_SMEM (QTILE + 3 * 2 * ATILE)   // 73728

__global__ __launch_bounds__(256, 2) void attn_mma_kernel(
    const __nv_bfloat16* __restrict__ Qb, const __nv_bfloat16* __restrict__ Kb,
    const __nv_bfloat16* __restrict__ Vb, __nv_bfloat16* __restrict__ O) {
    extern __shared__ char sma[];
    char* Qs = sma;
    int qi = blockIdx.x, bh = blockIdx.y;
    int b = bh >> 4, h = bh & 15;
    const __nv_bfloat16* Qg = Qb + (size_t)bh * NT * DH + (size_t)qi * 128 * DH;
    const __nv_bfloat16* Kg = Kb + (size_t)bh * NT * DH;
    const __nv_bfloat16* Vg = Vb + (size_t)bh * NT * DH;
    int tid = threadIdx.x, warp = tid >> 5, lane = tid & 31;
    int g = lane >> 2, tig = lane & 3;
    int ntile = (g_flags[b] && qi < 8) ? 16 : 20;

    auto load_kv = [&](int stage, int kt) {
        char* Ks = sma + QTILE + stage * 2 * ATILE;
        char* Vs = Ks + ATILE;
        const __nv_bfloat16* kg = Kg + (size_t)kt * 64 * DH;
        const __nv_bfloat16* vg = Vg + (size_t)kt * 64 * DH;
#pragma unroll
        for (int i = 0; i < 2; i++) {
            int cch = tid + i * 256;
            int row = cch >> 3, j = cch & 7;
            cp16(s32(Ks + row * KROW + j * 16), kg + row * DH + j * 8);
            cp16(s32(Vs + row * KROW + j * 16), vg + row * DH + j * 8);
        }
    };

#pragma unroll
    for (int i = 0; i < 4; i++) {
        int cch = tid + i * 256;
        int row = cch >> 3, j = cch & 7;
        cp16(s32(Qs + row * KROW + j * 16), Qg + row * DH + j * 8);
    }
    load_kv(0, 0); cp_commit();
    if (ntile > 1) load_kv(1, 1);
    cp_commit();

    uint32_t qf[4][4];
    float oacc[8][4];
#pragma unroll
    for (int j = 0; j < 8; j++)
#pragma unroll
        for (int v = 0; v < 4; v++) oacc[j][v] = 0.f;
    float m_g = -1e30f, m_g8 = -1e30f, l_g = 0.f, l_g8 = 0.f;

    int a_row = lane & 15, a_k8 = (lane >> 4) * 8;
    int b_k  = ((lane >> 3) & 1) * 8 + (lane & 7);
    int b_n8 = (lane >> 4) * 8;

    for (int kt = 0; kt < ntile; kt++) {
        cp_wait1();
        __syncthreads();
        if (kt + 2 < ntile) load_kv((kt + 2) % 3, kt + 2);
        cp_commit();
        const char* Ks = sma + QTILE + (kt % 3) * 2 * ATILE;
        const char* Vs = Ks + ATILE;

        if (kt == 0) {
#pragma unroll
            for (int ks = 0; ks < 4; ks++)
                ldsm4(qf[ks], s32(Qs + (warp * 16 + a_row) * KROW + (ks * 16 + a_k8) * 2));
        }

        float s[8][4];
#pragma unroll
        for (int j = 0; j < 8; j++)
#pragma unroll
            for (int v = 0; v < 4; v++) s[j][v] = 0.f;
#pragma unroll
        for (int ks = 0; ks < 4; ks++) {
#pragma unroll
            for (int jn2 = 0; jn2 < 4; jn2++) {
                uint32_t kf[4];
                ldsm4(kf, s32(Ks + (jn2 * 16 + a_row) * KROW + (ks * 16 + a_k8) * 2));
                uint32_t b0[2] = {kf[0], kf[2]};
                uint32_t b1[2] = {kf[1], kf[3]};
                mma_bf16(s[2 * jn2],     qf[ks], b0);
                mma_bf16(s[2 * jn2 + 1], qf[ks], b1);
            }
        }

        float mx0 = -1e30f, mx1 = -1e30f;
#pragma unroll
        for (int j = 0; j < 8; j++) {
            mx0 = fmaxf(mx0, fmaxf(s[j][0], s[j][1]));
            mx1 = fmaxf(mx1, fmaxf(s[j][2], s[j][3]));
        }
        mx0 = fmaxf(mx0, __shfl_xor_sync(0xffffffffu, mx0, 1));
        mx0 = fmaxf(mx0, __shfl_xor_sync(0xffffffffu, mx0, 2));
        mx1 = fmaxf(mx1, __shfl_xor_sync(0xffffffffu, mx1, 1));
        mx1 = fmaxf(mx1, __shfl_xor_sync(0xffffffffu, mx1, 2));
        float nm0 = fmaxf(m_g, mx0), nm1 = fmaxf(m_g8, mx1);
        float cr0 = __expf(m_g - nm0), cr1 = __expf(m_g8 - nm1);
        float ps0 = 0.f, ps1 = 0.f;
#pragma unroll
        for (int j = 0; j < 8; j++) {
            s[j][0] = __expf(s[j][0] - nm0);
            s[j][1] = __expf(s[j][1] - nm0);
            s[j][2] = __expf(s[j][2] - nm1);
            s[j][3] = __expf(s[j][3] - nm1);
            ps0 += s[j][0] + s[j][1];
            ps1 += s[j][2] + s[j][3];
        }
        ps0 += __shfl_xor_sync(0xffffffffu, ps0, 1);
        ps0 += __shfl_xor_sync(0xffffffffu, ps0, 2);
        ps1 += __shfl_xor_sync(0xffffffffu, ps1, 1);
        ps1 += __shfl_xor_sync(0xffffffffu, ps1, 2);
        l_g = l_g * cr0 + ps0;
        l_g8 = l_g8 * cr1 + ps1;
        m_g = nm0; m_g8 = nm1;
#pragma unroll
        for (int j = 0; j < 8; j++) {
            oacc[j][0] *= cr0; oacc[j][1] *= cr0;
            oacc[j][2] *= cr1; oacc[j][3] *= cr1;
        }

#pragma unroll
        for (int ki = 0; ki < 4; ki++) {
            uint32_t pa[4];
            __nv_bfloat162 t0 = __floats2bfloat162_rn(s[2 * ki][0], s[2 * ki][1]);
            __nv_bfloat162 t1 = __floats2bfloat162_rn(s[2 * ki][2], s[2 * ki][3]);
            __nv_bfloat162 t2 = __floats2bfloat162_rn(s[2 * ki + 1][0], s[2 * ki + 1][1]);
            __nv_bfloat162 t3 = __floats2bfloat162_rn(s[2 * ki + 1][2], s[2 * ki + 1][3]);
            memcpy(&pa[0], &t0, 4); memcpy(&pa[1], &t1, 4);
            memcpy(&pa[2], &t2, 4); memcpy(&pa[3], &t3, 4);
#pragma unroll
            for (int jn = 0; jn < 4; jn++) {
                uint32_t vf[4];
                ldsm4t(vf, s32(Vs + (ki * 16 + b_k) * KROW + (jn * 16 + b_n8) * 2));
                mma_bf16(oacc[2 * jn],     pa, &vf[0]);
                mma_bf16(oacc[2 * jn + 1], pa, &vf[2]);
            }
        }
        __syncthreads();
    }

    float inv0 = 1.f / l_g, inv1 = 1.f / l_g8;
    int t1 = b * NT + qi * 128 + warp * 16 + g;
    __nv_bfloat16* o1 = O + (size_t)t1 * C_ + h * DH;
    __nv_bfloat16* o2 = o1 + 8 * C_;
#pragma unroll
    for (int j = 0; j < 8; j++) {
        __nv_bfloat162 w0 = __floats2bfloat162_rn(oacc[j][0] * inv0, oacc[j][1] * inv0);
        __nv_bfloat162 w1 = __floats2bfloat162_rn(oacc[j][2] * inv1, oacc[j][3] * inv1);
        *(__nv_bfloat162*)&o1[j * 8 + 2 * tig] = w0;
        *(__nv_bfloat162*)&o2[j * 8 + 2 * tig] = w1;
    }
}

// ---------------- launch ----------------
extern "C" void kernel_launch(void* const* d_in, const int* in_sizes, int n_in,
                              void* d_out, int out_size) {
    const float* x_pixel = (const float*)d_in[0];
    const float* x_dino  = (const float*)d_in[1];
    const float* c       = (const float*)d_in[2];
    const float* w_ada_p = (const float*)d_in[3];
    const float* b_ada_p = (const float*)d_in[4];
    const float* w_ada_d = (const float*)d_in[5];
    const float* b_ada_d = (const float*)d_in[6];
    const float* g_n1p   = (const float*)d_in[7];
    const float* g_n1d   = (const float*)d_in[8];
    const float* g_n2p   = (const float*)d_in[9];
    const float* g_n2d   = (const float*)d_in[10];
    const float* w_qkv   = (const float*)d_in[11];
    const float* b_qkv   = (const float*)d_in[12];
    const float* g_qn    = (const float*)d_in[13];
    const float* g_kn    = (const float*)d_in[14];
    const float* w_proj  = (const float*)d_in[15];
    const float* b_proj  = (const float*)d_in[16];
    const float* w12_p   = (const float*)d_in[17];
    const float* b12_p   = (const float*)d_in[18];
    const float* w3_p    = (const float*)d_in[19];
    const float* b3_p    = (const float*)d_in[20];
    const float* w12_d   = (const float*)d_in[21];
    const float* b12_d   = (const float*)d_in[22];
    const float* w3_d    = (const float*)d_in[23];
    const float* b3_d    = (const float*)d_in[24];
    const void*  flags   = d_in[25];
    float* out = (float*)d_out;

    float* S = nullptr;
    cudaGetSymbolAddress((void**)&S, g_scratch);
    __nv_bfloat16* BF = nullptr;
    cudaGetSymbolAddress((void**)&BF, g_bf);

    float* ada  = S + OFF_ADA;
    float* xap  = S + OFF_XAP;
    float* xad  = S + OFF_XAD;

    __nv_bfloat16* xcb   = BF + BO_XC;
    __nv_bfloat16* attnb = BF + BO_ATTN;
    __nv_bfloat16* h2pb  = BF + BO_H2P;
    __nv_bfloat16* h2db  = BF + BO_H2D;
    __nv_bfloat16* glpb  = BF + BO_GLP;
    __nv_bfloat16* gldb  = BF + BO_GLD;
    __nv_bfloat16* qb    = BF + BO_QB;
    __nv_bfloat16* kb    = BF + BO_KB;
    __nv_bfloat16* vb    = BF + BO_VB;
    __nv_bfloat16* wqkvb = BF + BO_WQKV;
    __nv_bfloat16* wprjb = BF + BO_WPROJ;
    __nv_bfloat16* w12pb = BF + BO_W12P;
    __nv_bfloat16* w12db = BF + BO_W12D;
    __nv_bfloat16* w3pb  = BF + BO_W3P;
    __nv_bfloat16* w3db  = BF + BO_W3D;

    cudaFuncSetAttribute(bf16_gemm_kernel, cudaFuncAttributeMaxDynamicSharedMemorySize, GEMM_SMEM);
    cudaFuncSetAttribute(attn_mma_kernel, cudaFuncAttributeMaxDynamicSharedMemorySize, ATTN_SMEM);

    // ---- fork side stream: weight prep whose consumers are post-attention ----
    cudaStream_t s2;
    cudaStreamCreateWithFlags(&s2, cudaStreamNonBlocking);
    cudaEvent_t evFork, evJoin;
    cudaEventCreateWithFlags(&evFork, cudaEventDisableTiming);
    cudaEventCreateWithFlags(&evJoin, cudaEventDisableTiming);
    cudaEventRecord(evFork, 0);
    cudaStreamWaitEvent(s2, evFork, 0);

    wcvt_kernel<<<(int)(((size_t)C_ * C_ / 8 + 255) / 256), 256, 0, s2>>>(w_proj, wprjb, C_, C_);
    wperm12_kernel<<<dim3((int)(((size_t)C_ * N12I / 8 + 255) / 256), 2), 256, 0, s2>>>(w12_p, w12_d, w12pb, w12db);
    wcvt3_kernel<<<dim3((int)(((size_t)HIDP * C_ / 8 + 255) / 256), 2), 256, 0, s2>>>(w3_p, w3_d, w3pb, w3db);
    bperm_kernel<<<(N12I + 255) / 256, 256, 0, s2>>>(b12_p, b12_d);
    cudaEventRecord(evJoin, s2);

    // ---- critical path on default stream ----
    wcvt_kernel<<<(int)(((size_t)C_ * 3 * C_ / 8 + 255) / 256), 256>>>(w_qkv, wqkvb, C_, 3 * C_);
    prep_kernel<<<16, 256>>>(c, flags);
    ada_kernel<<<dim3(48, 2), 128>>>(w_ada_p, b_ada_p, w_ada_d, b_ada_d);

    norm_mod2_kernel<<<TOK, 256>>>(x_pixel, x_dino, g_n1p, g_n1d, ada, 0, 1,
                                   xcb, xcb, NT, 0, NT, NP);

    EpiParams e1 = {}; e1.mode = 1; e1.bias = b_qkv; e1.qbf = qb; e1.kbf = kb; e1.vbf = vb;
    bf16_gemm_kernel<<<dim3(24, 40), 256, GEMM_SMEM>>>(xcb, xcb, 1 << 30, wqkvb, wqkvb,
                                                       3 * C_, 3 * C_, C_, e1, e1);

    qknorm_rope_kernel<<<dim3(B_ * H_ * NT / 4, 2), 256>>>(qb, kb, g_qn, g_kn);

    attn_mma_kernel<<<dim3(10, 64), 256, ATTN_SMEM>>>(qb, kb, vb, attnb);

    // join side stream before proj GEMM (first consumer of wprjb; later GEMMs use w12/w3)
    cudaStreamWaitEvent(0, evJoin, 0);

    EpiParams e2 = {}; e2.mode = 2; e2.bias = b_proj; e2.xpix = x_pixel; e2.xdin = x_dino;
    e2.ada = ada; e2.xap = xap; e2.xad = xad;
    bf16_gemm_kernel<<<dim3(8, 40), 256, GEMM_SMEM>>>(attnb, attnb, 1 << 30, wprjb, wprjb,
                                                      C_, C_, C_, e2, e2);

    norm_mod2_kernel<<<TOK, 256>>>(xap, xad, g_n2p, g_n2d, ada, 3, 4,
                                   h2pb, h2db, NP, 0, ND, 0);

    EpiParams e3 = {}; e3.mode = 4; e3.bias = S + OFF_B12P; e3.glout = glpb;
    EpiParams e4 = {}; e4.mode = 4; e4.bias = S + OFF_B12D; e4.glout = gldb;
    bf16_gemm_kernel<<<dim3(43, 40), 256, GEMM_SMEM>>>(h2pb, h2db, 32, w12pb, w12db,
                                                       N12I, N12I, C_, e3, e4);

    EpiParams e5 = {}; e5.mode = 3; e5.bias = b3_p; e5.resid = xap;
    e5.gate = ada + 5 * C_; e5.rpb = NP; e5.out = out;
    EpiParams e6 = {}; e6.mode = 3; e6.bias = b3_d; e6.resid = xad;
    e6.gate = ada + 4 * 6144 + 5 * C_; e6.rpb = ND; e6.out = out + (size_t)PTOK * C_;
    bf16_gemm_kernel<<<dim3(8, 40), 256, GEMM_SMEM>>>(glpb, gldb, 32, w3pb, w3db,
                                                      C_, C_, HIDP, e5, e6);
}

// round 15
// speedup vs baseline: 1.0317x; 1.0257x over previous
#include <cuda_runtime.h>
#include <cuda_bf16.h>
#include <math.h>
#include <stdint.h>

#define B_  4
#define NP  1024
#define ND  256
#define NT  1280
#define C_  1024
#define H_  16
#define DH  64
#define HID 2730
#define HIDP 2752
#define N12  (2*HID)       // 5460
#define N12I (2*HIDP)      // 5504 (43*128)
#define TOK  (B_*NT)   // 5120
#define PTOK (B_*NP)   // 4096
#define DTOK (B_*ND)   // 1024

// ---------------- fp32 scratch ----------------
constexpr size_t OFF_SILU = 0;
constexpr size_t OFF_ADA  = OFF_SILU + 4096;
constexpr size_t OFF_XAP  = OFF_ADA  + 49152;
constexpr size_t OFF_XAD  = OFF_XAP  + (size_t)PTOK*C_;
constexpr size_t OFF_B12P = OFF_XAD  + (size_t)DTOK*C_;
constexpr size_t OFF_B12D = OFF_B12P + N12I;
constexpr size_t OFF_END  = OFF_B12D + N12I;

__device__ __align__(16) float g_scratch[OFF_END];
__device__ int g_flags[B_];

// ---------------- bf16 scratch ----------------
constexpr size_t BO_XC    = 0;
constexpr size_t BO_ATTN  = BO_XC    + (size_t)TOK*C_;
constexpr size_t BO_H2P   = BO_ATTN  + (size_t)TOK*C_;
constexpr size_t BO_H2D   = BO_H2P   + (size_t)PTOK*C_;
constexpr size_t BO_GLP   = BO_H2D   + (size_t)DTOK*C_;
constexpr size_t BO_GLD   = BO_GLP   + (size_t)PTOK*HIDP;
constexpr size_t BO_QB    = BO_GLD   + (size_t)DTOK*HIDP;
constexpr size_t BO_KB    = BO_QB    + (size_t)TOK*C_;
constexpr size_t BO_VB    = BO_KB    + (size_t)TOK*C_;
constexpr size_t BO_WQKV  = BO_VB    + (size_t)TOK*C_;
constexpr size_t BO_WPROJ = BO_WQKV  + (size_t)C_*3*C_;
constexpr size_t BO_W12P  = BO_WPROJ + (size_t)C_*C_;
constexpr size_t BO_W12D  = BO_W12P  + (size_t)C_*N12I;
constexpr size_t BO_W3P   = BO_W12D  + (size_t)C_*N12I;
constexpr size_t BO_W3D   = BO_W3P   + (size_t)HIDP*C_;
constexpr size_t BO_END   = BO_W3D   + (size_t)HIDP*C_;

__device__ __align__(16) __nv_bfloat16 g_bf[BO_END];

// ---------------- prep ----------------
__global__ void prep_kernel(const float* __restrict__ c, const void* __restrict__ flags) {
    int i = blockIdx.x * blockDim.x + threadIdx.x;
    if (i < B_ * C_) {
        float v = c[i];
        g_scratch[OFF_SILU + i] = v / (1.f + expf(-v));
    }
    if (blockIdx.x == 0 && threadIdx.x == 0) {
        const int* pi = (const int*)flags;
        const float* pf = (const float*)flags;
        const unsigned char* pc = (const unsigned char*)flags;
        bool iok = true, fok = true;
        for (int b = 0; b < B_; b++) {
            int t = pi[b]; if (t != 0 && t != 1) iok = false;
            float f = pf[b]; if (f != 0.f && f != 1.f) fok = false;
        }
        for (int b = 0; b < B_; b++)
            g_flags[b] = iok ? pi[b] : (fok ? (pf[b] != 0.f ? 1 : 0) : (pc[b] ? 1 : 0));
    }
}

// ---------------- pack helpers ----------------
__device__ __forceinline__ uint32_t packbf(float a, float b) {
    __nv_bfloat162 p = __floats2bfloat162_rn(a, b);
    uint32_t u; memcpy(&u, &p, 4); return u;
}

// ---------------- weight fp32 -> bf16, 8 elems/thread ----------------
__global__ void wcvt_kernel(const float* __restrict__ src, __nv_bfloat16* __restrict__ dst,
                            int src_rows, int cols) {
    size_t i8 = (size_t)blockIdx.x * blockDim.x + threadIdx.x;
    size_t i = i8 * 8;
    if (i >= (size_t)src_rows * cols) return;
    float4 v0 = *(const float4*)&src[i];
    float4 v1 = *(const float4*)&src[i + 4];
    uint4 o;
    o.x = packbf(v0.x, v0.y); o.y = packbf(v0.z, v0.w);
    o.z = packbf(v1.x, v1.y); o.w = packbf(v1.z, v1.w);
    *(uint4*)&dst[i] = o;
}

// ---------------- w3 convert+pad, both streams in one launch ----------------
__global__ void wcvt3_kernel(const float* __restrict__ srcp, const float* __restrict__ srcd,
                             __nv_bfloat16* __restrict__ dstp, __nv_bfloat16* __restrict__ dstd) {
    const float* src = blockIdx.y ? srcd : srcp;
    __nv_bfloat16* dst = blockIdx.y ? dstd : dstp;
    size_t i8 = (size_t)blockIdx.x * blockDim.x + threadIdx.x;
    size_t i = i8 * 8;
    if (i >= (size_t)HIDP * C_) return;
    int r = (int)(i / C_);
    uint4 o;
    if (r < HID) {
        float4 v0 = *(const float4*)&src[i];
        float4 v1 = *(const float4*)&src[i + 4];
        o.x = packbf(v0.x, v0.y); o.y = packbf(v0.z, v0.w);
        o.z = packbf(v1.x, v1.y); o.w = packbf(v1.z, v1.w);
    } else {
        o = make_uint4(0, 0, 0, 0);
    }
    *(uint4*)&dst[i] = o;
}

// ---------------- w12 permute+convert, both streams ----------------
__global__ void wperm12_kernel(const float* __restrict__ srcp, const float* __restrict__ srcd,
                               __nv_bfloat16* __restrict__ dstp, __nv_bfloat16* __restrict__ dstd) {
    const float* src = blockIdx.y ? srcd : srcp;
    __nv_bfloat16* dst = blockIdx.y ? dstd : dstp;
    size_t i8 = (size_t)blockIdx.x * blockDim.x + threadIdx.x;
    size_t i = i8 * 8;
    if (i >= (size_t)C_ * N12I) return;
    int r = (int)(i / N12I), c0 = (int)(i - (size_t)r * N12I);
    int j0 = c0 >> 1;
    uint4 o;
    if (j0 + 3 < HID) {
        float4 x1 = *(const float4*)&src[(size_t)r * N12 + j0];
        float2 x2a = *(const float2*)&src[(size_t)r * N12 + HID + j0];
        float2 x2b = *(const float2*)&src[(size_t)r * N12 + HID + j0 + 2];
        o.x = packbf(x1.x, x2a.x); o.y = packbf(x1.y, x2a.y);
        o.z = packbf(x1.z, x2b.x); o.w = packbf(x1.w, x2b.y);
    } else {
        float v[8];
#pragma unroll
        for (int t = 0; t < 4; t++) {
            int j = j0 + t;
            v[2 * t]     = (j < HID) ? src[(size_t)r * N12 + j] : 0.f;
            v[2 * t + 1] = (j < HID) ? src[(size_t)r * N12 + HID + j] : 0.f;
        }
        o.x = packbf(v[0], v[1]); o.y = packbf(v[2], v[3]);
        o.z = packbf(v[4], v[5]); o.w = packbf(v[6], v[7]);
    }
    *(uint4*)&dst[i] = o;
}

// ---------------- b12 permute ----------------
__global__ void bperm_kernel(const float* __restrict__ bp, const float* __restrict__ bd) {
    int j = blockIdx.x * blockDim.x + threadIdx.x;
    if (j >= N12I) return;
    int half = j & 1, jj = j >> 1;
    float vp = 0.f, vd = 0.f;
    if (jj < HID) {
        vp = bp[half ? HID + jj : jj];
        vd = bd[half ? HID + jj : jj];
    }
    g_scratch[OFF_B12P + j] = vp;
    g_scratch[OFF_B12D + j] = vd;
}

// ---------------- ada ----------------
__global__ void ada_kernel(const float* __restrict__ w_p, const float* __restrict__ b_p,
                           const float* __restrict__ w_d, const float* __restrict__ b_d) {
    int col = blockIdx.x * 128 + threadIdx.x;
    int st  = blockIdx.y;
    const float* w    = st ? w_d : w_p;
    const float* bias = st ? b_d : b_p;
    const float* sc = g_scratch + OFF_SILU;
    float a0 = 0, a1 = 0, a2 = 0, a3 = 0;
    for (int k = 0; k < C_; k++) {
        float wv = w[(size_t)k * 6144 + col];
        a0 += sc[k] * wv;
        a1 += sc[C_ + k] * wv;
        a2 += sc[2 * C_ + k] * wv;
        a3 += sc[3 * C_ + k] * wv;
    }
    float bv = bias[col];
    float* out = g_scratch + OFF_ADA + (size_t)st * 4 * 6144;
    out[0 * 6144 + col] = a0 + bv;
    out[1 * 6144 + col] = a1 + bv;
    out[2 * 6144 + col] = a2 + bv;
    out[3 * 6144 + col] = a3 + bv;
}

// ---------------- merged rms_norm + modulate (vectorized float4) ----------------
__global__ void norm_mod2_kernel(const float* __restrict__ xp, const float* __restrict__ xd,
                                 const float* __restrict__ gp, const float* __restrict__ gd,
                                 const float* __restrict__ ada, int sh_chunk, int sc_chunk,
                                 __nv_bfloat16* __restrict__ outp, __nv_bfloat16* __restrict__ outd,
                                 int bsp, int offp, int bsd, int offd) {
    int row = blockIdx.x;
    const float* x; const float* g; const float* adab; __nv_bfloat16* out;
    int Nseg, bstride, ooff;
    if (row < PTOK) {
        x = xp; g = gp; adab = ada; out = outp; Nseg = NP; bstride = bsp; ooff = offp;
    } else {
        row -= PTOK;
        x = xd; g = gd; adab = ada + 4 * 6144; out = outd; Nseg = ND; bstride = bsd; ooff = offd;
    }
    int b = row / Nseg, n = row - b * Nseg;
    const float* xr = x + (size_t)row * C_;
    __nv_bfloat16* orow = out + ((size_t)b * bstride + ooff + n) * C_;
    const float* ar = adab + (size_t)b * 6144;
    int tid = threadIdx.x;
    int cc0 = tid * 4;
    float4 xv = *(const float4*)&xr[cc0];
    float ss = xv.x * xv.x + xv.y * xv.y + xv.z * xv.z + xv.w * xv.w;
#pragma unroll
    for (int o = 16; o; o >>= 1) ss += __shfl_xor_sync(0xffffffffu, ss, o);
    __shared__ float red[8];
    if ((tid & 31) == 0) red[tid >> 5] = ss;
    __syncthreads();
    float tot = 0.f;
#pragma unroll
    for (int w = 0; w < 8; w++) tot += red[w];
    float r = rsqrtf(tot * (1.f / C_) + 1e-6f);
    float4 gv = *(const float4*)&g[cc0];
    float4 sc4 = *(const float4*)&ar[sc_chunk * C_ + cc0];
    float4 sh4 = *(const float4*)&ar[sh_chunk * C_ + cc0];
    float o0 = xv.x * r * gv.x * (1.f + sc4.x) + sh4.x;
    float o1 = xv.y * r * gv.y * (1.f + sc4.y) + sh4.y;
    float o2 = xv.z * r * gv.z * (1.f + sc4.z) + sh4.z;
    float o3 = xv.w * r * gv.w * (1.f + sc4.w) + sh4.w;
    *(uint2*)&orow[cc0] = make_uint2(packbf(o0, o1), packbf(o2, o3));
}

// ---------------- per-head rmsnorm + rope on bf16, q/k split by blockIdx.y ---------
__global__ void qknorm_rope_kernel(__nv_bfloat16* __restrict__ Q, __nv_bfloat16* __restrict__ Kp,
                                   const float* __restrict__ gq, const float* __restrict__ gk) {
    int sub = threadIdx.x >> 6;
    int idx = blockIdx.x * 4 + sub;
    int n = idx % NT;
    int d = threadIdx.x & 63;
    int pos = n < NP ? n : n - NP;
    __shared__ float sh[4][64];
    __shared__ float red[4][2];
    int i2 = d < 32 ? d : d - 32;
    float inv = expf(-logf(10000.f) * (2.f * i2) * (1.f / 64.f));
    float sv, cv;
    sincosf((float)pos * inv, &sv, &cv);
    int pass = blockIdx.y;
    __nv_bfloat16* ptr = (pass ? Kp : Q) + (size_t)idx * 64;
    const float* g = pass ? gk : gq;
    float x = __bfloat162float(ptr[d]);
    float ss = x * x;
#pragma unroll
    for (int o = 16; o; o >>= 1) ss += __shfl_xor_sync(0xffffffffu, ss, o);
    if ((d & 31) == 0) red[sub][d >> 5] = ss;
    __syncthreads();
    float tot = red[sub][0] + red[sub][1];
    float v = x * rsqrtf(tot * (1.f / 64.f) + 1e-6f) * g[d];
    sh[sub][d] = v;
    __syncthreads();
    float x1 = sh[sub][i2], x2 = sh[sub][i2 + 32];
    float rr = (d < 32) ? (x1 * cv - x2 * sv) : (x1 * sv + x2 * cv);
    if (pass == 0) rr *= 0.125f;
    ptr[d] = __float2bfloat16(rr);
}

// ---------------- epilogue params ----------------
struct EpiParams {
    int mode;                 // 1=qkv scatter(bf16), 2=proj residual, 3=final, 4=swiglu
    const float* bias;
    float* out;
    __nv_bfloat16* qbf; __nv_bfloat16* kbf; __nv_bfloat16* vbf;
    __nv_bfloat16* glout;
    const float* resid;
    const float* gate;
    int rpb;
    const float* xpix; const float* xdin; const float* ada;
    float* xap; float* xad;
};

// vectorized pair store: cc even, cc+1 in same row, N multiple of 128 (no bounds)
__device__ __forceinline__ void epi_store2(const EpiParams& ep, int N, int r, int cc,
                                           float v0, float v1) {
    v0 += ep.bias[cc];
    v1 += ep.bias[cc + 1];
    if (ep.mode == 1) {
        int bb_ = r / NT, nn = r - bb_ * NT;
        int m = cc >> 10, rem = cc & 1023, h = rem >> 6, d = rem & 63;
        size_t dst = (((size_t)(bb_ * H_ + h) * NT) + nn) * DH + d;
        __nv_bfloat16* base = (m == 0) ? ep.qbf : (m == 1 ? ep.kbf : ep.vbf);
        *(__nv_bfloat162*)&base[dst] = __floats2bfloat162_rn(v0, v1);
    } else if (ep.mode == 2) {
        int bb_ = r / NT, nn = r - bb_ * NT;
        float2 g2 = *(const float2*)&ep.ada[(nn < NP ? bb_ * 6144 : 4 * 6144 + bb_ * 6144) + 2 * C_ + cc];
        if (nn < NP) {
            size_t idx = (size_t)(bb_ * NP + nn) * C_ + cc;
            float2 x2 = *(const float2*)&ep.xpix[idx];
            *(float2*)&ep.xap[idx] = make_float2(x2.x + g2.x * v0, x2.y + g2.y * v1);
        } else {
            size_t idx = (size_t)(bb_ * ND + nn - NP) * C_ + cc;
            float2 x2 = *(const float2*)&ep.xdin[idx];
            *(float2*)&ep.xad[idx] = make_float2(x2.x + g2.x * v0, x2.y + g2.y * v1);
        }
    } else {
        int bb_ = r / ep.rpb;
        size_t idx = (size_t)r * N + cc;
        float2 r2 = *(const float2*)&ep.resid[idx];
        float2 g2 = *(const float2*)&ep.gate[bb_ * 6144 + cc];
        *(float2*)&ep.out[idx] = make_float2(r2.x + g2.x * v0, r2.y + g2.y * v1);
    }
}

// ---------------- asm helpers ----------------
__device__ __forceinline__ uint32_t s32(const void* p) {
    return (uint32_t)__cvta_generic_to_shared(p);
}
__device__ __forceinline__ void cp16(uint32_t dst, const void* src) {
    asm volatile("cp.async.cg.shared.global [%0], [%1], 16;" :: "r"(dst), "l"(src));
}
__device__ __forceinline__ void cp16p(uint32_t dst, const void* src, bool pred) {
    int sz = pred ? 16 : 0;
    asm volatile("cp.async.cg.shared.global [%0], [%1], 16, %2;" :: "r"(dst), "l"(src), "r"(sz));
}
__device__ __forceinline__ void cp_commit() { asm volatile("cp.async.commit_group;"); }
__device__ __forceinline__ void cp_wait1() { asm volatile("cp.async.wait_group 1;"); }

__device__ __forceinline__ void ldsm4(uint32_t* r, uint32_t a) {
    asm volatile("ldmatrix.sync.aligned.m8n8.x4.shared.b16 {%0,%1,%2,%3}, [%4];"
                 : "=r"(r[0]), "=r"(r[1]), "=r"(r[2]), "=r"(r[3]) : "r"(a));
}
__device__ __forceinline__ void ldsm4t(uint32_t* r, uint32_t a) {
    asm volatile("ldmatrix.sync.aligned.m8n8.x4.trans.shared.b16 {%0,%1,%2,%3}, [%4];"
                 : "=r"(r[0]), "=r"(r[1]), "=r"(r[2]), "=r"(r[3]) : "r"(a));
}
__device__ __forceinline__ void mma_bf16(float* d, const uint32_t* a, const uint32_t* b) {
    asm volatile(
        "mma.sync.aligned.m16n8k16.row.col.f32.bf16.bf16.f32 "
        "{%0,%1,%2,%3}, {%4,%5,%6,%7}, {%8,%9}, {%0,%1,%2,%3};"
        : "+f"(d[0]), "+f"(d[1]), "+f"(d[2]), "+f"(d[3])
        : "r"(a[0]), "r"(a[1]), "r"(a[2]), "r"(a[3]), "r"(b[0]), "r"(b[1]));
}

// ---------------- bf16 tensor-core GEMM, 128x128x32, 3-stage ----------------
#define AROWB 80
#define BROWB 272
#define A_BYTES (128 * AROWB)
#define B_BYTES (32 * BROWB)
#define STAGE_B (A_BYTES + B_BYTES)
#define NSTAGE 3
#define GEMM_SMEM (NSTAGE * STAGE_B)

__global__ __launch_bounds__(256, 2) void bf16_gemm_kernel(
    const __nv_bfloat16* __restrict__ A, const __nv_bfloat16* __restrict__ A2, int blkM1,
    const __nv_bfloat16* __restrict__ Bw, const __nv_bfloat16* __restrict__ Bw2,
    int Nreal, int Npad, int Kpad, EpiParams ep, EpiParams ep2) {
    extern __shared__ char smem[];
    int tid = threadIdx.x;
    int warp = tid >> 5, lane = tid & 31;
    int wm = warp >> 2, wn = warp & 3;
    int g = lane >> 2, tig = lane & 3;
    bool seg2 = (int)blockIdx.y >= blkM1;
    const __nv_bfloat16* Ause = seg2 ? A2 : A;
    const __nv_bfloat16* Buse = seg2 ? Bw2 : Bw;
    int row0 = (seg2 ? blockIdx.y - blkM1 : blockIdx.y) * 128;
    int col0 = blockIdx.x * 128;
    int nkt = Kpad >> 5;

    float acc[4][4][4];
#pragma unroll
    for (int mi = 0; mi < 4; mi++)
#pragma unroll
        for (int ni = 0; ni < 4; ni++)
#pragma unroll
            for (int v = 0; v < 4; v++) acc[mi][ni][v] = 0.f;

    auto load_tile = [&](int stage, int kt) {
        int kb = kt * 32;
        char* As = smem + stage * STAGE_B;
        char* Bs = As + A_BYTES;
#pragma unroll
        for (int i = 0; i < 2; i++) {
            int cch = tid + i * 256;
            int row = cch >> 2, j = cch & 3;
            cp16(s32(As + row * AROWB + j * 16),
                 Ause + (size_t)(row0 + row) * Kpad + kb + j * 8);
        }
#pragma unroll
        for (int i = 0; i < 2; i++) {
            int cch = tid + i * 256;
            int kr = cch >> 4, j = cch & 15;
            int col = col0 + j * 8;
            cp16p(s32(Bs + kr * BROWB + j * 16),
                  Buse + (size_t)(kb + kr) * Npad + col, col < Npad);
        }
    };

    load_tile(0, 0); cp_commit();
    if (nkt > 1) load_tile(1, 1);
    cp_commit();

    int a_row = lane & 15, a_k8 = (lane >> 4) * 8;
    int b_k  = ((lane >> 3) & 1) * 8 + (lane & 7);
    int b_n8 = (lane >> 4) * 8;

    for (int kt = 0; kt < nkt; kt++) {
        cp_wait1();
        __syncthreads();
        if (kt + 2 < nkt) load_tile((kt + 2) % NSTAGE, kt + 2);
        cp_commit();
        const char* As = smem + (kt % NSTAGE) * STAGE_B;
        const char* Bs = As + A_BYTES;
#pragma unroll
        for (int ks = 0; ks < 2; ks++) {
            uint32_t a[4][4], b[2][4];
#pragma unroll
            for (int mi = 0; mi < 4; mi++)
                ldsm4(a[mi], s32(As + (wm * 64 + mi * 16 + a_row) * AROWB
                                    + (ks * 16 + a_k8) * 2));
#pragma unroll
            for (int nb = 0; nb < 2; nb++)
                ldsm4t(b[nb], s32(Bs + (ks * 16 + b_k) * BROWB
                                     + (wn * 32 + nb * 16 + b_n8) * 2));
#pragma unroll
            for (int mi = 0; mi < 4; mi++)
#pragma unroll
                for (int ni = 0; ni < 4; ni++)
                    mma_bf16(acc[mi][ni], a[mi], &b[ni >> 1][(ni & 1) * 2]);
        }
        __syncthreads();
    }

    const EpiParams& epu = seg2 ? ep2 : ep;
    if (epu.mode == 4) {
#pragma unroll
        for (int mi = 0; mi < 4; mi++) {
            int r1 = row0 + wm * 64 + mi * 16 + g;
            int r2 = r1 + 8;
#pragma unroll
            for (int ni = 0; ni < 4; ni++) {
                int cc0 = col0 + wn * 32 + ni * 8 + 2 * tig;
                float b0 = epu.bias[cc0], b1 = epu.bias[cc0 + 1];
                float x1a = acc[mi][ni][0] + b0, x2a = acc[mi][ni][1] + b1;
                float x1b = acc[mi][ni][2] + b0, x2b = acc[mi][ni][3] + b1;
                float ga = x1a / (1.f + __expf(-x1a)) * x2a;
                float gb = x1b / (1.f + __expf(-x1b)) * x2b;
                epu.glout[(size_t)r1 * HIDP + (cc0 >> 1)] = __float2bfloat16(ga);
                epu.glout[(size_t)r2 * HIDP + (cc0 >> 1)] = __float2bfloat16(gb);
            }
        }
        return;
    }

#pragma unroll
    for (int mi = 0; mi < 4; mi++) {
        int r1 = row0 + wm * 64 + mi * 16 + g;
        int r2 = r1 + 8;
#pragma unroll
        for (int ni = 0; ni < 4; ni++) {
            int cc0 = col0 + wn * 32 + ni * 8 + 2 * tig;
            epi_store2(epu, Nreal, r1, cc0, acc[mi][ni][0], acc[mi][ni][1]);
            epi_store2(epu, Nreal, r2, cc0, acc[mi][ni][2], acc[mi][ni][3]);
        }
    }
}

// ---------------- tensor-core flash attention: 128-row Q tiles, 256 threads ----------
#define KROW 144
#define ATILE (64 * KROW)
#define QTILE (128 * KROW)
#define ATTN_SMEM (QTILE + 3 * 2 * ATILE)   // 73728

__global__ __launch_bounds__(256, 2) void attn_mma_kernel(
    const __nv_bfloat16* __restrict__ Qb, const __nv_bfloat16* __restrict__ Kb,
    const __nv_bfloat16* __restrict__ Vb, __nv_bfloat16* __restrict__ O) {
    extern __shared__ char sma[];
    char* Qs = sma;
    int qi = blockIdx.x, bh = blockIdx.y;
    int b = bh >> 4, h = bh & 15;
    const __nv_bfloat16* Qg = Qb + (size_t)bh * NT * DH + (size_t)qi * 128 * DH;
    const __nv_bfloat16* Kg = Kb + (size_t)bh * NT * DH;
    const __nv_bfloat16* Vg = Vb + (size_t)bh * NT * DH;
    int tid = threadIdx.x, warp = tid >> 5, lane = tid & 31;
    int g = lane >> 2, tig = lane & 3;
    int ntile = (g_flags[b] && qi < 8) ? 16 : 20;

    auto load_kv = [&](int stage, int kt) {
        char* Ks = sma + QTILE + stage * 2 * ATILE;
        char* Vs = Ks + ATILE;
        const __nv_bfloat16* kg = Kg + (size_t)kt * 64 * DH;
        const __nv_bfloat16* vg = Vg + (size_t)kt * 64 * DH;
#pragma unroll
        for (int i = 0; i < 2; i++) {
            int cch = tid + i * 256;
            int row = cch >> 3, j = cch & 7;
            cp16(s32(Ks + row * KROW + j * 16), kg + row * DH + j * 8);
            cp16(s32(Vs + row * KROW + j * 16), vg + row * DH + j * 8);
        }
    };

#pragma unroll
    for (int i = 0; i < 4; i++) {
        int cch = tid + i * 256;
        int row = cch >> 3, j = cch & 7;
        cp16(s32(Qs + row * KROW + j * 16), Qg + row * DH + j * 8);
    }
    load_kv(0, 0); cp_commit();
    if (ntile > 1) load_kv(1, 1);
    cp_commit();

    uint32_t qf[4][4];
    float oacc[8][4];
#pragma unroll
    for (int j = 0; j < 8; j++)
#pragma unroll
        for (int v = 0; v < 4; v++) oacc[j][v] = 0.f;
    float m_g = -1e30f, m_g8 = -1e30f, l_g = 0.f, l_g8 = 0.f;

    int a_row = lane & 15, a_k8 = (lane >> 4) * 8;
    int b_k  = ((lane >> 3) & 1) * 8 + (lane & 7);
    int b_n8 = (lane >> 4) * 8;

    for (int kt = 0; kt < ntile; kt++) {
        cp_wait1();
        __syncthreads();
        if (kt + 2 < ntile) load_kv((kt + 2) % 3, kt + 2);
        cp_commit();
        const char* Ks = sma + QTILE + (kt % 3) * 2 * ATILE;
        const char* Vs = Ks + ATILE;

        if (kt == 0) {
#pragma unroll
            for (int ks = 0; ks < 4; ks++)
                ldsm4(qf[ks], s32(Qs + (warp * 16 + a_row) * KROW + (ks * 16 + a_k8) * 2));
        }

        float s[8][4];
#pragma unroll
        for (int j = 0; j < 8; j++)
#pragma unroll
            for (int v = 0; v < 4; v++) s[j][v] = 0.f;
#pragma unroll
        for (int ks = 0; ks < 4; ks++) {
#pragma unroll
            for (int jn2 = 0; jn2 < 4; jn2++) {
                uint32_t kf[4];
                ldsm4(kf, s32(Ks + (jn2 * 16 + a_row) * KROW + (ks * 16 + a_k8) * 2));
                uint32_t b0[2] = {kf[0], kf[2]};
                uint32_t b1[2] = {kf[1], kf[3]};
                mma_bf16(s[2 * jn2],     qf[ks], b0);
                mma_bf16(s[2 * jn2 + 1], qf[ks], b1);
            }
        }

        float mx0 = -1e30f, mx1 = -1e30f;
#pragma unroll
        for (int j = 0; j < 8; j++) {
            mx0 = fmaxf(mx0, fmaxf(s[j][0], s[j][1]));
            mx1 = fmaxf(mx1, fmaxf(s[j][2], s[j][3]));
        }
        mx0 = fmaxf(mx0, __shfl_xor_sync(0xffffffffu, mx0, 1));
        mx0 = fmaxf(mx0, __shfl_xor_sync(0xffffffffu, mx0, 2));
        mx1 = fmaxf(mx1, __shfl_xor_sync(0xffffffffu, mx1, 1));
        mx1 = fmaxf(mx1, __shfl_xor_sync(0xffffffffu, mx1, 2));
        float nm0 = fmaxf(m_g, mx0), nm1 = fmaxf(m_g8, mx1);
        float cr0 = __expf(m_g - nm0), cr1 = __expf(m_g8 - nm1);
        float ps0 = 0.f, ps1 = 0.f;
#pragma unroll
        for (int j = 0; j < 8; j++) {
            s[j][0] = __expf(s[j][0] - nm0);
            s[j][1] = __expf(s[j][1] - nm0);
            s[j][2] = __expf(s[j][2] - nm1);
            s[j][3] = __expf(s[j][3] - nm1);
            ps0 += s[j][0] + s[j][1];
            ps1 += s[j][2] + s[j][3];
        }
        ps0 += __shfl_xor_sync(0xffffffffu, ps0, 1);
        ps0 += __shfl_xor_sync(0xffffffffu, ps0, 2);
        ps1 += __shfl_xor_sync(0xffffffffu, ps1, 1);
        ps1 += __shfl_xor_sync(0xffffffffu, ps1, 2);
        l_g = l_g * cr0 + ps0;
        l_g8 = l_g8 * cr1 + ps1;
        m_g = nm0; m_g8 = nm1;
#pragma unroll
        for (int j = 0; j < 8; j++) {
            oacc[j][0] *= cr0; oacc[j][1] *= cr0;
            oacc[j][2] *= cr1; oacc[j][3] *= cr1;
        }

#pragma unroll
        for (int ki = 0; ki < 4; ki++) {
            uint32_t pa[4];
            __nv_bfloat162 t0 = __floats2bfloat162_rn(s[2 * ki][0], s[2 * ki][1]);
            __nv_bfloat162 t1 = __floats2bfloat162_rn(s[2 * ki][2], s[2 * ki][3]);
            __nv_bfloat162 t2 = __floats2bfloat162_rn(s[2 * ki + 1][0], s[2 * ki + 1][1]);
            __nv_bfloat162 t3 = __floats2bfloat162_rn(s[2 * ki + 1][2], s[2 * ki + 1][3]);
            memcpy(&pa[0], &t0, 4); memcpy(&pa[1], &t1, 4);
            memcpy(&pa[2], &t2, 4); memcpy(&pa[3], &t3, 4);
#pragma unroll
            for (int jn = 0; jn < 4; jn++) {
                uint32_t vf[4];
                ldsm4t(vf, s32(Vs + (ki * 16 + b_k) * KROW + (jn * 16 + b_n8) * 2));
                mma_bf16(oacc[2 * jn],     pa, &vf[0]);
                mma_bf16(oacc[2 * jn + 1], pa, &vf[2]);
            }
        }
        __syncthreads();
    }

    float inv0 = 1.f / l_g, inv1 = 1.f / l_g8;
    int t1 = b * NT + qi * 128 + warp * 16 + g;
    __nv_bfloat16* o1 = O + (size_t)t1 * C_ + h * DH;
    __nv_bfloat16* o2 = o1 + 8 * C_;
#pragma unroll
    for (int j = 0; j < 8; j++) {
        __nv_bfloat162 w0 = __floats2bfloat162_rn(oacc[j][0] * inv0, oacc[j][1] * inv0);
        __nv_bfloat162 w1 = __floats2bfloat162_rn(oacc[j][2] * inv1, oacc[j][3] * inv1);
        *(__nv_bfloat162*)&o1[j * 8 + 2 * tig] = w0;
        *(__nv_bfloat162*)&o2[j * 8 + 2 * tig] = w1;
    }
}

// ---------------- launch ----------------
extern "C" void kernel_launch(void* const* d_in, const int* in_sizes, int n_in,
                              void* d_out, int out_size) {
    const float* x_pixel = (const float*)d_in[0];
    const float* x_dino  = (const float*)d_in[1];
    const float* c       = (const float*)d_in[2];
    const float* w_ada_p = (const float*)d_in[3];
    const float* b_ada_p = (const float*)d_in[4];
    const float* w_ada_d = (const float*)d_in[5];
    const float* b_ada_d = (const float*)d_in[6];
    const float* g_n1p   = (const float*)d_in[7];
    const float* g_n1d   = (const float*)d_in[8];
    const float* g_n2p   = (const float*)d_in[9];
    const float* g_n2d   = (const float*)d_in[10];
    const float* w_qkv   = (const float*)d_in[11];
    const float* b_qkv   = (const float*)d_in[12];
    const float* g_qn    = (const float*)d_in[13];
    const float* g_kn    = (const float*)d_in[14];
    const float* w_proj  = (const float*)d_in[15];
    const float* b_proj  = (const float*)d_in[16];
    const float* w12_p   = (const float*)d_in[17];
    const float* b12_p   = (const float*)d_in[18];
    const float* w3_p    = (const float*)d_in[19];
    const float* b3_p    = (const float*)d_in[20];
    const float* w12_d   = (const float*)d_in[21];
    const float* b12_d   = (const float*)d_in[22];
    const float* w3_d    = (const float*)d_in[23];
    const float* b3_d    = (const float*)d_in[24];
    const void*  flags   = d_in[25];
    float* out = (float*)d_out;

    float* S = nullptr;
    cudaGetSymbolAddress((void**)&S, g_scratch);
    __nv_bfloat16* BF = nullptr;
    cudaGetSymbolAddress((void**)&BF, g_bf);

    float* ada  = S + OFF_ADA;
    float* xap  = S + OFF_XAP;
    float* xad  = S + OFF_XAD;

    __nv_bfloat16* xcb   = BF + BO_XC;
    __nv_bfloat16* attnb = BF + BO_ATTN;
    __nv_bfloat16* h2pb  = BF + BO_H2P;
    __nv_bfloat16* h2db  = BF + BO_H2D;
    __nv_bfloat16* glpb  = BF + BO_GLP;
    __nv_bfloat16* gldb  = BF + BO_GLD;
    __nv_bfloat16* qb    = BF + BO_QB;
    __nv_bfloat16* kb    = BF + BO_KB;
    __nv_bfloat16* vb    = BF + BO_VB;
    __nv_bfloat16* wqkvb = BF + BO_WQKV;
    __nv_bfloat16* wprjb = BF + BO_WPROJ;
    __nv_bfloat16* w12pb = BF + BO_W12P;
    __nv_bfloat16* w12db = BF + BO_W12D;
    __nv_bfloat16* w3pb  = BF + BO_W3P;
    __nv_bfloat16* w3db  = BF + BO_W3D;

    cudaFuncSetAttribute(bf16_gemm_kernel, cudaFuncAttributeMaxDynamicSharedMemorySize, GEMM_SMEM);
    cudaFuncSetAttribute(attn_mma_kernel, cudaFuncAttributeMaxDynamicSharedMemorySize, ATTN_SMEM);

    // ---- fork side stream: weight prep whose consumers are post-attention ----
    cudaStream_t s2;
    cudaStreamCreateWithFlags(&s2, cudaStreamNonBlocking);
    cudaEvent_t evFork, evJoin;
    cudaEventCreateWithFlags(&evFork, cudaEventDisableTiming);
    cudaEventCreateWithFlags(&evJoin, cudaEventDisableTiming);
    cudaEventRecord(evFork, 0);
    cudaStreamWaitEvent(s2, evFork, 0);

    wcvt_kernel<<<(int)(((size_t)C_ * C_ / 8 + 255) / 256), 256, 0, s2>>>(w_proj, wprjb, C_, C_);
    wperm12_kernel<<<dim3((int)(((size_t)C_ * N12I / 8 + 255) / 256), 2), 256, 0, s2>>>(w12_p, w12_d, w12pb, w12db);
    wcvt3_kernel<<<dim3((int)(((size_t)HIDP * C_ / 8 + 255) / 256), 2), 256, 0, s2>>>(w3_p, w3_d, w3pb, w3db);
    bperm_kernel<<<(N12I + 255) / 256, 256, 0, s2>>>(b12_p, b12_d);
    cudaEventRecord(evJoin, s2);

    // ---- critical path on default stream ----
    wcvt_kernel<<<(int)(((size_t)C_ * 3 * C_ / 8 + 255) / 256), 256>>>(w_qkv, wqkvb, C_, 3 * C_);
    prep_kernel<<<16, 256>>>(c, flags);
    ada_kernel<<<dim3(48, 2), 128>>>(w_ada_p, b_ada_p, w_ada_d, b_ada_d);

    norm_mod2_kernel<<<TOK, 256>>>(x_pixel, x_dino, g_n1p, g_n1d, ada, 0, 1,
                                   xcb, xcb, NT, 0, NT, NP);

    EpiParams e1 = {}; e1.mode = 1; e1.bias = b_qkv; e1.qbf = qb; e1.kbf = kb; e1.vbf = vb;
    bf16_gemm_kernel<<<dim3(24, 40), 256, GEMM_SMEM>>>(xcb, xcb, 1 << 30, wqkvb, wqkvb,
                                                       3 * C_, 3 * C_, C_, e1, e1);

    qknorm_rope_kernel<<<dim3(B_ * H_ * NT / 4, 2), 256>>>(qb, kb, g_qn, g_kn);

    attn_mma_kernel<<<dim3(10, 64), 256, ATTN_SMEM>>>(qb, kb, vb, attnb);

    // join side stream before proj GEMM
    cudaStreamWaitEvent(0, evJoin, 0);

    EpiParams e2 = {}; e2.mode = 2; e2.bias = b_proj; e2.xpix = x_pixel; e2.xdin = x_dino;
    e2.ada = ada; e2.xap = xap; e2.xad = xad;
    bf16_gemm_kernel<<<dim3(8, 40), 256, GEMM_SMEM>>>(attnb, attnb, 1 << 30, wprjb, wprjb,
                                                      C_, C_, C_, e2, e2);

    norm_mod2_kernel<<<TOK, 256>>>(xap, xad, g_n2p, g_n2d, ada, 3, 4,
                                   h2pb, h2db, NP, 0, ND, 0);

    EpiParams e3 = {}; e3.mode = 4; e3.bias = S + OFF_B12P; e3.glout = glpb;
    EpiParams e4 = {}; e4.mode = 4; e4.bias = S + OFF_B12D; e4.glout = gldb;
    bf16_gemm_kernel<<<dim3(43, 40), 256, GEMM_SMEM>>>(h2pb, h2db, 32, w12pb, w12db,
                                                       N12I, N12I, C_, e3, e4);

    EpiParams e5 = {}; e5.mode = 3; e5.bias = b3_p; e5.resid = xap;
    e5.gate = ada + 5 * C_; e5.rpb = NP; e5.out = out;
    EpiParams e6 = {}; e6.mode = 3; e6.bias = b3_d; e6.resid = xad;
    e6.gate = ada + 4 * 6144 + 5 * C_; e6.rpb = ND; e6.out = out + (size_t)PTOK * C_;
    bf16_gemm_kernel<<<dim3(8, 40), 256, GEMM_SMEM>>>(glpb, gldb, 32, w3pb, w3db,
                                                      C_, C_, HIDP, e5, e6);
}

// round 17
// speedup vs baseline: 1.0662x; 1.0334x over previous
#include <cuda_runtime.h>
#include <cuda_bf16.h>
#include <math.h>
#include <stdint.h>

#define B_  4
#define NP  1024
#define ND  256
#define NT  1280
#define C_  1024
#define H_  16
#define DH  64
#define HID 2730
#define HIDP 2752
#define N12  (2*HID)       // 5460
#define N12I (2*HIDP)      // 5504 (43*128)
#define TOK  (B_*NT)   // 5120
#define PTOK (B_*NP)   // 4096
#define DTOK (B_*ND)   // 1024

// ---------------- fp32 scratch ----------------
constexpr size_t OFF_SILU = 0;
constexpr size_t OFF_ADA  = OFF_SILU + 4096;
constexpr size_t OFF_XAP  = OFF_ADA  + 49152;
constexpr size_t OFF_XAD  = OFF_XAP  + (size_t)PTOK*C_;
constexpr size_t OFF_B12P = OFF_XAD  + (size_t)DTOK*C_;
constexpr size_t OFF_B12D = OFF_B12P + N12I;
constexpr size_t OFF_END  = OFF_B12D + N12I;

__device__ __align__(16) float g_scratch[OFF_END];
__device__ int g_flags[B_];

// ---------------- bf16 scratch ----------------
constexpr size_t BO_XC    = 0;
constexpr size_t BO_ATTN  = BO_XC    + (size_t)TOK*C_;
constexpr size_t BO_H2P   = BO_ATTN  + (size_t)TOK*C_;
constexpr size_t BO_H2D   = BO_H2P   + (size_t)PTOK*C_;
constexpr size_t BO_GLP   = BO_H2D   + (size_t)DTOK*C_;
constexpr size_t BO_GLD   = BO_GLP   + (size_t)PTOK*HIDP;
constexpr size_t BO_QB    = BO_GLD   + (size_t)DTOK*HIDP;
constexpr size_t BO_KB    = BO_QB    + (size_t)TOK*C_;
constexpr size_t BO_VB    = BO_KB    + (size_t)TOK*C_;
constexpr size_t BO_WQKV  = BO_VB    + (size_t)TOK*C_;
constexpr size_t BO_WPROJ = BO_WQKV  + (size_t)C_*3*C_;
constexpr size_t BO_W12P  = BO_WPROJ + (size_t)C_*C_;
constexpr size_t BO_W12D  = BO_W12P  + (size_t)C_*N12I;
constexpr size_t BO_W3P   = BO_W12D  + (size_t)C_*N12I;
constexpr size_t BO_W3D   = BO_W3P   + (size_t)HIDP*C_;
constexpr size_t BO_END   = BO_W3D   + (size_t)HIDP*C_;

__device__ __align__(16) __nv_bfloat16 g_bf[BO_END];

// ---------------- prep ----------------
__global__ void prep_kernel(const float* __restrict__ c, const void* __restrict__ flags) {
    int i = blockIdx.x * blockDim.x + threadIdx.x;
    if (i < B_ * C_) {
        float v = c[i];
        g_scratch[OFF_SILU + i] = v / (1.f + expf(-v));
    }
    if (blockIdx.x == 0 && threadIdx.x == 0) {
        const int* pi = (const int*)flags;
        const float* pf = (const float*)flags;
        const unsigned char* pc = (const unsigned char*)flags;
        bool iok = true, fok = true;
        for (int b = 0; b < B_; b++) {
            int t = pi[b]; if (t != 0 && t != 1) iok = false;
            float f = pf[b]; if (f != 0.f && f != 1.f) fok = false;
        }
        for (int b = 0; b < B_; b++)
            g_flags[b] = iok ? pi[b] : (fok ? (pf[b] != 0.f ? 1 : 0) : (pc[b] ? 1 : 0));
    }
}

// ---------------- pack helpers ----------------
__device__ __forceinline__ uint32_t packbf(float a, float b) {
    __nv_bfloat162 p = __floats2bfloat162_rn(a, b);
    uint32_t u; memcpy(&u, &p, 4); return u;
}

// ---------------- weight fp32 -> bf16, 8 elems/thread ----------------
__global__ void wcvt_kernel(const float* __restrict__ src, __nv_bfloat16* __restrict__ dst,
                            int src_rows, int cols) {
    size_t i8 = (size_t)blockIdx.x * blockDim.x + threadIdx.x;
    size_t i = i8 * 8;
    if (i >= (size_t)src_rows * cols) return;
    float4 v0 = *(const float4*)&src[i];
    float4 v1 = *(const float4*)&src[i + 4];
    uint4 o;
    o.x = packbf(v0.x, v0.y); o.y = packbf(v0.z, v0.w);
    o.z = packbf(v1.x, v1.y); o.w = packbf(v1.z, v1.w);
    *(uint4*)&dst[i] = o;
}

// ---------------- w3 convert+pad, both streams in one launch ----------------
__global__ void wcvt3_kernel(const float* __restrict__ srcp, const float* __restrict__ srcd,
                             __nv_bfloat16* __restrict__ dstp, __nv_bfloat16* __restrict__ dstd) {
    const float* src = blockIdx.y ? srcd : srcp;
    __nv_bfloat16* dst = blockIdx.y ? dstd : dstp;
    size_t i8 = (size_t)blockIdx.x * blockDim.x + threadIdx.x;
    size_t i = i8 * 8;
    if (i >= (size_t)HIDP * C_) return;
    int r = (int)(i / C_);
    uint4 o;
    if (r < HID) {
        float4 v0 = *(const float4*)&src[i];
        float4 v1 = *(const float4*)&src[i + 4];
        o.x = packbf(v0.x, v0.y); o.y = packbf(v0.z, v0.w);
        o.z = packbf(v1.x, v1.y); o.w = packbf(v1.z, v1.w);
    } else {
        o = make_uint4(0, 0, 0, 0);
    }
    *(uint4*)&dst[i] = o;
}

// ---------------- w12 permute+convert, both streams ----------------
__global__ void wperm12_kernel(const float* __restrict__ srcp, const float* __restrict__ srcd,
                               __nv_bfloat16* __restrict__ dstp, __nv_bfloat16* __restrict__ dstd) {
    const float* src = blockIdx.y ? srcd : srcp;
    __nv_bfloat16* dst = blockIdx.y ? dstd : dstp;
    size_t i8 = (size_t)blockIdx.x * blockDim.x + threadIdx.x;
    size_t i = i8 * 8;
    if (i >= (size_t)C_ * N12I) return;
    int r = (int)(i / N12I), c0 = (int)(i - (size_t)r * N12I);
    int j0 = c0 >> 1;
    uint4 o;
    if (j0 + 3 < HID) {
        float4 x1 = *(const float4*)&src[(size_t)r * N12 + j0];
        float2 x2a = *(const float2*)&src[(size_t)r * N12 + HID + j0];
        float2 x2b = *(const float2*)&src[(size_t)r * N12 + HID + j0 + 2];
        o.x = packbf(x1.x, x2a.x); o.y = packbf(x1.y, x2a.y);
        o.z = packbf(x1.z, x2b.x); o.w = packbf(x1.w, x2b.y);
    } else {
        float v[8];
#pragma unroll
        for (int t = 0; t < 4; t++) {
            int j = j0 + t;
            v[2 * t]     = (j < HID) ? src[(size_t)r * N12 + j] : 0.f;
            v[2 * t + 1] = (j < HID) ? src[(size_t)r * N12 + HID + j] : 0.f;
        }
        o.x = packbf(v[0], v[1]); o.y = packbf(v[2], v[3]);
        o.z = packbf(v[4], v[5]); o.w = packbf(v[6], v[7]);
    }
    *(uint4*)&dst[i] = o;
}

// ---------------- b12 permute ----------------
__global__ void bperm_kernel(const float* __restrict__ bp, const float* __restrict__ bd) {
    int j = blockIdx.x * blockDim.x + threadIdx.x;
    if (j >= N12I) return;
    int half = j & 1, jj = j >> 1;
    float vp = 0.f, vd = 0.f;
    if (jj < HID) {
        vp = bp[half ? HID + jj : jj];
        vd = bd[half ? HID + jj : jj];
    }
    g_scratch[OFF_B12P + j] = vp;
    g_scratch[OFF_B12D + j] = vd;
}

// ---------------- ada ----------------
__global__ void ada_kernel(const float* __restrict__ w_p, const float* __restrict__ b_p,
                           const float* __restrict__ w_d, const float* __restrict__ b_d) {
    int col = blockIdx.x * 128 + threadIdx.x;
    int st  = blockIdx.y;
    const float* w    = st ? w_d : w_p;
    const float* bias = st ? b_d : b_p;
    const float* sc = g_scratch + OFF_SILU;
    float a0 = 0, a1 = 0, a2 = 0, a3 = 0;
#pragma unroll 8
    for (int k = 0; k < C_; k++) {
        float wv = w[(size_t)k * 6144 + col];
        a0 += sc[k] * wv;
        a1 += sc[C_ + k] * wv;
        a2 += sc[2 * C_ + k] * wv;
        a3 += sc[3 * C_ + k] * wv;
    }
    float bv = bias[col];
    float* out = g_scratch + OFF_ADA + (size_t)st * 4 * 6144;
    out[0 * 6144 + col] = a0 + bv;
    out[1 * 6144 + col] = a1 + bv;
    out[2 * 6144 + col] = a2 + bv;
    out[3 * 6144 + col] = a3 + bv;
}

// ---------------- merged rms_norm + modulate (vectorized float4) ----------------
__global__ void norm_mod2_kernel(const float* __restrict__ xp, const float* __restrict__ xd,
                                 const float* __restrict__ gp, const float* __restrict__ gd,
                                 const float* __restrict__ ada, int sh_chunk, int sc_chunk,
                                 __nv_bfloat16* __restrict__ outp, __nv_bfloat16* __restrict__ outd,
                                 int bsp, int offp, int bsd, int offd) {
    int row = blockIdx.x;
    const float* x; const float* g; const float* adab; __nv_bfloat16* out;
    int Nseg, bstride, ooff;
    if (row < PTOK) {
        x = xp; g = gp; adab = ada; out = outp; Nseg = NP; bstride = bsp; ooff = offp;
    } else {
        row -= PTOK;
        x = xd; g = gd; adab = ada + 4 * 6144; out = outd; Nseg = ND; bstride = bsd; ooff = offd;
    }
    int b = row / Nseg, n = row - b * Nseg;
    const float* xr = x + (size_t)row * C_;
    __nv_bfloat16* orow = out + ((size_t)b * bstride + ooff + n) * C_;
    const float* ar = adab + (size_t)b * 6144;
    int tid = threadIdx.x;
    int cc0 = tid * 4;
    float4 xv = *(const float4*)&xr[cc0];
    float ss = xv.x * xv.x + xv.y * xv.y + xv.z * xv.z + xv.w * xv.w;
#pragma unroll
    for (int o = 16; o; o >>= 1) ss += __shfl_xor_sync(0xffffffffu, ss, o);
    __shared__ float red[8];
    if ((tid & 31) == 0) red[tid >> 5] = ss;
    __syncthreads();
    float tot = 0.f;
#pragma unroll
    for (int w = 0; w < 8; w++) tot += red[w];
    float r = rsqrtf(tot * (1.f / C_) + 1e-6f);
    float4 gv = *(const float4*)&g[cc0];
    float4 sc4 = *(const float4*)&ar[sc_chunk * C_ + cc0];
    float4 sh4 = *(const float4*)&ar[sh_chunk * C_ + cc0];
    float o0 = xv.x * r * gv.x * (1.f + sc4.x) + sh4.x;
    float o1 = xv.y * r * gv.y * (1.f + sc4.y) + sh4.y;
    float o2 = xv.z * r * gv.z * (1.f + sc4.z) + sh4.z;
    float o3 = xv.w * r * gv.w * (1.f + sc4.w) + sh4.w;
    *(uint2*)&orow[cc0] = make_uint2(packbf(o0, o1), packbf(o2, o3));
}

// ---------------- warp-per-token rmsnorm + rope on bf16 ----------------
__global__ void qknorm_rope_kernel(__nv_bfloat16* __restrict__ Q, __nv_bfloat16* __restrict__ Kp,
                                   const float* __restrict__ gq, const float* __restrict__ gk) {
    int warp = threadIdx.x >> 5, lane = threadIdx.x & 31;
    int idx = blockIdx.x * 8 + warp;
    int n = idx % NT;
    int pos = n < NP ? n : n - NP;
    int pass = blockIdx.y;
    __nv_bfloat16* ptr = (pass ? Kp : Q) + (size_t)idx * 64;
    const float* g = pass ? gk : gq;
    int d0 = 2 * lane;
    __nv_bfloat162 xv2 = *(__nv_bfloat162*)&ptr[d0];
    float x0 = __bfloat162float(xv2.x), x1 = __bfloat162float(xv2.y);
    float ss = x0 * x0 + x1 * x1;
#pragma unroll
    for (int o = 16; o; o >>= 1) ss += __shfl_xor_sync(0xffffffffu, ss, o);
    float rinv = rsqrtf(ss * (1.f / 64.f) + 1e-6f);
    float2 g2 = *(const float2*)&g[d0];
    float v0 = x0 * rinv * g2.x, v1 = x1 * rinv * g2.y;
    float p0 = __shfl_xor_sync(0xffffffffu, v0, 16);
    float p1 = __shfl_xor_sync(0xffffffffu, v1, 16);
    int j0 = (lane < 16) ? d0 : d0 - 32;
    float sv0, cv0, sv1, cv1;
    float inva = expf(-logf(10000.f) * (2.f * j0) * (1.f / 64.f));
    float invb = expf(-logf(10000.f) * (2.f * (j0 + 1)) * (1.f / 64.f));
    sincosf((float)pos * inva, &sv0, &cv0);
    sincosf((float)pos * invb, &sv1, &cv1);
    float rr0, rr1;
    if (lane < 16) {
        rr0 = v0 * cv0 - p0 * sv0;
        rr1 = v1 * cv1 - p1 * sv1;
    } else {
        rr0 = p0 * sv0 + v0 * cv0;
        rr1 = p1 * sv1 + v1 * cv1;
    }
    if (pass == 0) { rr0 *= 0.125f; rr1 *= 0.125f; }
    *(__nv_bfloat162*)&ptr[d0] = __floats2bfloat162_rn(rr0, rr1);
}

// ---------------- epilogue params ----------------
struct EpiParams {
    int mode;                 // 1=qkv scatter(bf16), 2=proj residual, 3=final, 4=swiglu
    const float* bias;
    float* out;
    __nv_bfloat16* qbf; __nv_bfloat16* kbf; __nv_bfloat16* vbf;
    __nv_bfloat16* glout;
    const float* resid;
    const float* gate;
    int rpb;
    const float* xpix; const float* xdin; const float* ada;
    float* xap; float* xad;
};

__device__ __forceinline__ void epi_store2(const EpiParams& ep, int N, int r, int cc,
                                           float v0, float v1) {
    v0 += ep.bias[cc];
    v1 += ep.bias[cc + 1];
    if (ep.mode == 1) {
        int bb_ = r / NT, nn = r - bb_ * NT;
        int m = cc >> 10, rem = cc & 1023, h = rem >> 6, d = rem & 63;
        size_t dst = (((size_t)(bb_ * H_ + h) * NT) + nn) * DH + d;
        __nv_bfloat16* base = (m == 0) ? ep.qbf : (m == 1 ? ep.kbf : ep.vbf);
        *(__nv_bfloat162*)&base[dst] = __floats2bfloat162_rn(v0, v1);
    } else if (ep.mode == 2) {
        int bb_ = r / NT, nn = r - bb_ * NT;
        float2 g2 = *(const float2*)&ep.ada[(nn < NP ? bb_ * 6144 : 4 * 6144 + bb_ * 6144) + 2 * C_ + cc];
        if (nn < NP) {
            size_t idx = (size_t)(bb_ * NP + nn) * C_ + cc;
            float2 x2 = *(const float2*)&ep.xpix[idx];
            *(float2*)&ep.xap[idx] = make_float2(x2.x + g2.x * v0, x2.y + g2.y * v1);
        } else {
            size_t idx = (size_t)(bb_ * ND + nn - NP) * C_ + cc;
            float2 x2 = *(const float2*)&ep.xdin[idx];
            *(float2*)&ep.xad[idx] = make_float2(x2.x + g2.x * v0, x2.y + g2.y * v1);
        }
    } else {
        int bb_ = r / ep.rpb;
        size_t idx = (size_t)r * N + cc;
        float2 r2 = *(const float2*)&ep.resid[idx];
        float2 g2 = *(const float2*)&ep.gate[bb_ * 6144 + cc];
        *(float2*)&ep.out[idx] = make_float2(r2.x + g2.x * v0, r2.y + g2.y * v1);
    }
}

// ---------------- asm helpers ----------------
__device__ __forceinline__ uint32_t s32(const void* p) {
    return (uint32_t)__cvta_generic_to_shared(p);
}
__device__ __forceinline__ void cp16(uint32_t dst, const void* src) {
    asm volatile("cp.async.cg.shared.global [%0], [%1], 16;" :: "r"(dst), "l"(src));
}
__device__ __forceinline__ void cp16p(uint32_t dst, const void* src, bool pred) {
    int sz = pred ? 16 : 0;
    asm volatile("cp.async.cg.shared.global [%0], [%1], 16, %2;" :: "r"(dst), "l"(src), "r"(sz));
}
__device__ __forceinline__ void cp_commit() { asm volatile("cp.async.commit_group;"); }
__device__ __forceinline__ void cp_wait1() { asm volatile("cp.async.wait_group 1;"); }

__device__ __forceinline__ void ldsm4(uint32_t* r, uint32_t a) {
    asm volatile("ldmatrix.sync.aligned.m8n8.x4.shared.b16 {%0,%1,%2,%3}, [%4];"
                 : "=r"(r[0]), "=r"(r[1]), "=r"(r[2]), "=r"(r[3]) : "r"(a));
}
__device__ __forceinline__ void ldsm4t(uint32_t* r, uint32_t a) {
    asm volatile("ldmatrix.sync.aligned.m8n8.x4.trans.shared.b16 {%0,%1,%2,%3}, [%4];"
                 : "=r"(r[0]), "=r"(r[1]), "=r"(r[2]), "=r"(r[3]) : "r"(a));
}
__device__ __forceinline__ void mma_bf16(float* d, const uint32_t* a, const uint32_t* b) {
    asm volatile(
        "mma.sync.aligned.m16n8k16.row.col.f32.bf16.bf16.f32 "
        "{%0,%1,%2,%3}, {%4,%5,%6,%7}, {%8,%9}, {%0,%1,%2,%3};"
        : "+f"(d[0]), "+f"(d[1]), "+f"(d[2]), "+f"(d[3])
        : "r"(a[0]), "r"(a[1]), "r"(a[2]), "r"(a[3]), "r"(b[0]), "r"(b[1]));
}

// ---------------- bf16 tensor-core GEMM, 128x128x32, 3-stage ----------------
#define AROWB 80
#define BROWB 272
#define A_BYTES (128 * AROWB)
#define B_BYTES (32 * BROWB)
#define STAGE_B (A_BYTES + B_BYTES)
#define NSTAGE 3
#define GEMM_SMEM (NSTAGE * STAGE_B)

__global__ __launch_bounds__(256, 2) void bf16_gemm_kernel(
    const __nv_bfloat16* __restrict__ A, const __nv_bfloat16* __restrict__ A2, int blkM1,
    const __nv_bfloat16* __restrict__ Bw, const __nv_bfloat16* __restrict__ Bw2,
    int Nreal, int Npad, int Kpad, EpiParams ep, EpiParams ep2) {
    extern __shared__ char smem[];
    int tid = threadIdx.x;
    int warp = tid >> 5, lane = tid & 31;
    int wm = warp >> 2, wn = warp & 3;
    int g = lane >> 2, tig = lane & 3;
    bool seg2 = (int)blockIdx.y >= blkM1;
    const __nv_bfloat16* Ause = seg2 ? A2 : A;
    const __nv_bfloat16* Buse = seg2 ? Bw2 : Bw;
    int row0 = (seg2 ? blockIdx.y - blkM1 : blockIdx.y) * 128;
    int col0 = blockIdx.x * 128;
    int nkt = Kpad >> 5;

    float acc[4][4][4];
#pragma unroll
    for (int mi = 0; mi < 4; mi++)
#pragma unroll
        for (int ni = 0; ni < 4; ni++)
#pragma unroll
            for (int v = 0; v < 4; v++) acc[mi][ni][v] = 0.f;

    auto load_tile = [&](int stage, int kt) {
        int kb = kt * 32;
        char* As = smem + stage * STAGE_B;
        char* Bs = As + A_BYTES;
#pragma unroll
        for (int i = 0; i < 2; i++) {
            int cch = tid + i * 256;
            int row = cch >> 2, j = cch & 3;
            cp16(s32(As + row * AROWB + j * 16),
                 Ause + (size_t)(row0 + row) * Kpad + kb + j * 8);
        }
#pragma unroll
        for (int i = 0; i < 2; i++) {
            int cch = tid + i * 256;
            int kr = cch >> 4, j = cch & 15;
            int col = col0 + j * 8;
            cp16p(s32(Bs + kr * BROWB + j * 16),
                  Buse + (size_t)(kb + kr) * Npad + col, col < Npad);
        }
    };

    load_tile(0, 0); cp_commit();
    if (nkt > 1) load_tile(1, 1);
    cp_commit();

    int a_row = lane & 15, a_k8 = (lane >> 4) * 8;
    int b_k  = ((lane >> 3) & 1) * 8 + (lane & 7);
    int b_n8 = (lane >> 4) * 8;

    for (int kt = 0; kt < nkt; kt++) {
        cp_wait1();
        __syncthreads();
        if (kt + 2 < nkt) load_tile((kt + 2) % NSTAGE, kt + 2);
        cp_commit();
        const char* As = smem + (kt % NSTAGE) * STAGE_B;
        const char* Bs = As + A_BYTES;
#pragma unroll
        for (int ks = 0; ks < 2; ks++) {
            uint32_t a[4][4], b[2][4];
#pragma unroll
            for (int mi = 0; mi < 4; mi++)
                ldsm4(a[mi], s32(As + (wm * 64 + mi * 16 + a_row) * AROWB
                                    + (ks * 16 + a_k8) * 2));
#pragma unroll
            for (int nb = 0; nb < 2; nb++)
                ldsm4t(b[nb], s32(Bs + (ks * 16 + b_k) * BROWB
                                     + (wn * 32 + nb * 16 + b_n8) * 2));
#pragma unroll
            for (int mi = 0; mi < 4; mi++)
#pragma unroll
                for (int ni = 0; ni < 4; ni++)
                    mma_bf16(acc[mi][ni], a[mi], &b[ni >> 1][(ni & 1) * 2]);
        }
        __syncthreads();
    }

    const EpiParams& epu = seg2 ? ep2 : ep;
    if (epu.mode == 4) {
#pragma unroll
        for (int mi = 0; mi < 4; mi++) {
            int r1 = row0 + wm * 64 + mi * 16 + g;
            int r2 = r1 + 8;
#pragma unroll
            for (int ni = 0; ni < 4; ni++) {
                int cc0 = col0 + wn * 32 + ni * 8 + 2 * tig;
                float b0 = epu.bias[cc0], b1 = epu.bias[cc0 + 1];
                float x1a = acc[mi][ni][0] + b0, x2a = acc[mi][ni][1] + b1;
                float x1b = acc[mi][ni][2] + b0, x2b = acc[mi][ni][3] + b1;
                float ga = x1a / (1.f + __expf(-x1a)) * x2a;
                float gb = x1b / (1.f + __expf(-x1b)) * x2b;
                epu.glout[(size_t)r1 * HIDP + (cc0 >> 1)] = __float2bfloat16(ga);
                epu.glout[(size_t)r2 * HIDP + (cc0 >> 1)] = __float2bfloat16(gb);
            }
        }
        return;
    }

#pragma unroll
    for (int mi = 0; mi < 4; mi++) {
        int r1 = row0 + wm * 64 + mi * 16 + g;
        int r2 = r1 + 8;
#pragma unroll
        for (int ni = 0; ni < 4; ni++) {
            int cc0 = col0 + wn * 32 + ni * 8 + 2 * tig;
            epi_store2(epu, Nreal, r1, cc0, acc[mi][ni][0], acc[mi][ni][1]);
            epi_store2(epu, Nreal, r2, cc0, acc[mi][ni][2], acc[mi][ni][3]);
        }
    }
}

// ---------------- tensor-core flash attention: 128-row Q tiles, 256 threads ----------
#define KROW 144
#define ATILE (64 * KROW)
#define QTILE (128 * KROW)
#define ATTN_SMEM (QTILE + 3 * 2 * ATILE)   // 73728

__global__ __launch_bounds__(256, 2) void attn_mma_kernel(
    const __nv_bfloat16* __restrict__ Qb, const __nv_bfloat16* __restrict__ Kb,
    const __nv_bfloat16* __restrict__ Vb, __nv_bfloat16* __restrict__ O) {
    extern __shared__ char sma[];
    char* Qs = sma;
    int qi = blockIdx.x, bh = blockIdx.y;
    int b = bh >> 4, h = bh & 15;
    const __nv_bfloat16* Qg = Qb + (size_t)bh * NT * DH + (size_t)qi * 128 * DH;
    const __nv_bfloat16* Kg = Kb + (size_t)bh * NT * DH;
    const __nv_bfloat16* Vg = Vb + (size_t)bh * NT * DH;
    int tid = threadIdx.x, warp = tid >> 5, lane = tid & 31;
    int g = lane >> 2, tig = lane & 3;
    int ntile = (g_flags[b] && qi < 8) ? 16 : 20;

    auto load_kv = [&](int stage, int kt) {
        char* Ks = sma + QTILE + stage * 2 * ATILE;
        char* Vs = Ks + ATILE;
        const __nv_bfloat16* kg = Kg + (size_t)kt * 64 * DH;
        const __nv_bfloat16* vg = Vg + (size_t)kt * 64 * DH;
#pragma unroll
        for (int i = 0; i < 2; i++) {
            int cch = tid + i * 256;
            int row = cch >> 3, j = cch & 7;
            cp16(s32(Ks + row * KROW + j * 16), kg + row * DH + j * 8);
            cp16(s32(Vs + row * KROW + j * 16), vg + row * DH + j * 8);
        }
    };

#pragma unroll
    for (int i = 0; i < 4; i++) {
        int cch = tid + i * 256;
        int row = cch >> 3, j = cch & 7;
        cp16(s32(Qs + row * KROW + j * 16), Qg + row * DH + j * 8);
    }
    load_kv(0, 0); cp_commit();
    if (ntile > 1) load_kv(1, 1);
    cp_commit();

    uint32_t qf[4][4];
    float oacc[8][4];
#pragma unroll
    for (int j = 0; j < 8; j++)
#pragma unroll
        for (int v = 0; v < 4; v++) oacc[j][v] = 0.f;
    float m_g = -1e30f, m_g8 = -1e30f, l_g = 0.f, l_g8 = 0.f;

    int a_row = lane & 15, a_k8 = (lane >> 4) * 8;
    int b_k  = ((lane >> 3) & 1) * 8 + (lane & 7);
    int b_n8 = (lane >> 4) * 8;

    for (int kt = 0; kt < ntile; kt++) {
        cp_wait1();
        __syncthreads();
        if (kt + 2 < ntile) load_kv((kt + 2) % 3, kt + 2);
        cp_commit();
        const char* Ks = sma + QTILE + (kt % 3) * 2 * ATILE;
        const char* Vs = Ks + ATILE;

        if (kt == 0) {
#pragma unroll
            for (int ks = 0; ks < 4; ks++)
                ldsm4(qf[ks], s32(Qs + (warp * 16 + a_row) * KROW + (ks * 16 + a_k8) * 2));
        }

        float s[8][4];
#pragma unroll
        for (int j = 0; j < 8; j++)
#pragma unroll
            for (int v = 0; v < 4; v++) s[j][v] = 0.f;
#pragma unroll
        for (int ks = 0; ks < 4; ks++) {
#pragma unroll
            for (int jn2 = 0; jn2 < 4; jn2++) {
                uint32_t kf[4];
                ldsm4(kf, s32(Ks + (jn2 * 16 + a_row) * KROW + (ks * 16 + a_k8) * 2));
                uint32_t b0[2] = {kf[0], kf[2]};
                uint32_t b1[2] = {kf[1], kf[3]};
                mma_bf16(s[2 * jn2],     qf[ks], b0);
                mma_bf16(s[2 * jn2 + 1], qf[ks], b1);
            }
        }

        float mx0 = -1e30f, mx1 = -1e30f;
#pragma unroll
        for (int j = 0; j < 8; j++) {
            mx0 = fmaxf(mx0, fmaxf(s[j][0], s[j][1]));
            mx1 = fmaxf(mx1, fmaxf(s[j][2], s[j][3]));
        }
        mx0 = fmaxf(mx0, __shfl_xor_sync(0xffffffffu, mx0, 1));
        mx0 = fmaxf(mx0, __shfl_xor_sync(0xffffffffu, mx0, 2));
        mx1 = fmaxf(mx1, __shfl_xor_sync(0xffffffffu, mx1, 1));
        mx1 = fmaxf(mx1, __shfl_xor_sync(0xffffffffu, mx1, 2));
        float nm0 = fmaxf(m_g, mx0), nm1 = fmaxf(m_g8, mx1);
        float cr0 = __expf(m_g - nm0), cr1 = __expf(m_g8 - nm1);
        float ps0 = 0.f, ps1 = 0.f;
#pragma unroll
        for (int j = 0; j < 8; j++) {
            s[j][0] = __expf(s[j][0] - nm0);
            s[j][1] = __expf(s[j][1] - nm0);
            s[j][2] = __expf(s[j][2] - nm1);
            s[j][3] = __expf(s[j][3] - nm1);
            ps0 += s[j][0] + s[j][1];
            ps1 += s[j][2] + s[j][3];
        }
        ps0 += __shfl_xor_sync(0xffffffffu, ps0, 1);
        ps0 += __shfl_xor_sync(0xffffffffu, ps0, 2);
        ps1 += __shfl_xor_sync(0xffffffffu, ps1, 1);
        ps1 += __shfl_xor_sync(0xffffffffu, ps1, 2);
        l_g = l_g * cr0 + ps0;
        l_g8 = l_g8 * cr1 + ps1;
        m_g = nm0; m_g8 = nm1;
#pragma unroll
        for (int j = 0; j < 8; j++) {
            oacc[j][0] *= cr0; oacc[j][1] *= cr0;
            oacc[j][2] *= cr1; oacc[j][3] *= cr1;
        }

#pragma unroll
        for (int ki = 0; ki < 4; ki++) {
            uint32_t pa[4];
            __nv_bfloat162 t0 = __floats2bfloat162_rn(s[2 * ki][0], s[2 * ki][1]);
            __nv_bfloat162 t1 = __floats2bfloat162_rn(s[2 * ki][2], s[2 * ki][3]);
            __nv_bfloat162 t2 = __floats2bfloat162_rn(s[2 * ki + 1][0], s[2 * ki + 1][1]);
            __nv_bfloat162 t3 = __floats2bfloat162_rn(s[2 * ki + 1][2], s[2 * ki + 1][3]);
            memcpy(&pa[0], &t0, 4); memcpy(&pa[1], &t1, 4);
            memcpy(&pa[2], &t2, 4); memcpy(&pa[3], &t3, 4);
#pragma unroll
            for (int jn = 0; jn < 4; jn++) {
                uint32_t vf[4];
                ldsm4t(vf, s32(Vs + (ki * 16 + b_k) * KROW + (jn * 16 + b_n8) * 2));
                mma_bf16(oacc[2 * jn],     pa, &vf[0]);
                mma_bf16(oacc[2 * jn + 1], pa, &vf[2]);
            }
        }
        __syncthreads();
    }

    float inv0 = 1.f / l_g, inv1 = 1.f / l_g8;
    int t1 = b * NT + qi * 128 + warp * 16 + g;
    __nv_bfloat16* o1 = O + (size_t)t1 * C_ + h * DH;
    __nv_bfloat16* o2 = o1 + 8 * C_;
#pragma unroll
    for (int j = 0; j < 8; j++) {
        __nv_bfloat162 w0 = __floats2bfloat162_rn(oacc[j][0] * inv0, oacc[j][1] * inv0);
        __nv_bfloat162 w1 = __floats2bfloat162_rn(oacc[j][2] * inv1, oacc[j][3] * inv1);
        *(__nv_bfloat162*)&o1[j * 8 + 2 * tig] = w0;
        *(__nv_bfloat162*)&o2[j * 8 + 2 * tig] = w1;
    }
}

// ---------------- launch ----------------
extern "C" void kernel_launch(void* const* d_in, const int* in_sizes, int n_in,
                              void* d_out, int out_size) {
    const float* x_pixel = (const float*)d_in[0];
    const float* x_dino  = (const float*)d_in[1];
    const float* c       = (const float*)d_in[2];
    const float* w_ada_p = (const float*)d_in[3];
    const float* b_ada_p = (const float*)d_in[4];
    const float* w_ada_d = (const float*)d_in[5];
    const float* b_ada_d = (const float*)d_in[6];
    const float* g_n1p   = (const float*)d_in[7];
    const float* g_n1d   = (const float*)d_in[8];
    const float* g_n2p   = (const float*)d_in[9];
    const float* g_n2d   = (const float*)d_in[10];
    const float* w_qkv   = (const float*)d_in[11];
    const float* b_qkv   = (const float*)d_in[12];
    const float* g_qn    = (const float*)d_in[13];
    const float* g_kn    = (const float*)d_in[14];
    const float* w_proj  = (const float*)d_in[15];
    const float* b_proj  = (const float*)d_in[16];
    const float* w12_p   = (const float*)d_in[17];
    const float* b12_p   = (const float*)d_in[18];
    const float* w3_p    = (const float*)d_in[19];
    const float* b3_p    = (const float*)d_in[20];
    const float* w12_d   = (const float*)d_in[21];
    const float* b12_d   = (const float*)d_in[22];
    const float* w3_d    = (const float*)d_in[23];
    const float* b3_d    = (const float*)d_in[24];
    const void*  flags   = d_in[25];
    float* out = (float*)d_out;

    float* S = nullptr;
    cudaGetSymbolAddress((void**)&S, g_scratch);
    __nv_bfloat16* BF = nullptr;
    cudaGetSymbolAddress((void**)&BF, g_bf);

    float* ada  = S + OFF_ADA;
    float* xap  = S + OFF_XAP;
    float* xad  = S + OFF_XAD;

    __nv_bfloat16* xcb   = BF + BO_XC;
    __nv_bfloat16* attnb = BF + BO_ATTN;
    __nv_bfloat16* h2pb  = BF + BO_H2P;
    __nv_bfloat16* h2db  = BF + BO_H2D;
    __nv_bfloat16* glpb  = BF + BO_GLP;
    __nv_bfloat16* gldb  = BF + BO_GLD;
    __nv_bfloat16* qb    = BF + BO_QB;
    __nv_bfloat16* kb    = BF + BO_KB;
    __nv_bfloat16* vb    = BF + BO_VB;
    __nv_bfloat16* wqkvb = BF + BO_WQKV;
    __nv_bfloat16* wprjb = BF + BO_WPROJ;
    __nv_bfloat16* w12pb = BF + BO_W12P;
    __nv_bfloat16* w12db = BF + BO_W12D;
    __nv_bfloat16* w3pb  = BF + BO_W3P;
    __nv_bfloat16* w3db  = BF + BO_W3D;

    cudaFuncSetAttribute(bf16_gemm_kernel, cudaFuncAttributeMaxDynamicSharedMemorySize, GEMM_SMEM);
    cudaFuncSetAttribute(attn_mma_kernel, cudaFuncAttributeMaxDynamicSharedMemorySize, ATTN_SMEM);

    // ---- fork streams (destroyed at end of this call to restore mem baseline) ----
    cudaStream_t s2, s3;
    cudaStreamCreateWithFlags(&s2, cudaStreamNonBlocking);
    cudaStreamCreateWithFlags(&s3, cudaStreamNonBlocking);
    cudaEvent_t evFork, evJoin, evQkvW;
    cudaEventCreateWithFlags(&evFork, cudaEventDisableTiming);
    cudaEventCreateWithFlags(&evJoin, cudaEventDisableTiming);
    cudaEventCreateWithFlags(&evQkvW, cudaEventDisableTiming);
    cudaEventRecord(evFork, 0);
    cudaStreamWaitEvent(s2, evFork, 0);
    cudaStreamWaitEvent(s3, evFork, 0);

    // s3: qkv weight convert (joins before QKV GEMM)
    wcvt_kernel<<<(int)(((size_t)C_ * 3 * C_ / 8 + 255) / 256), 256, 0, s3>>>(w_qkv, wqkvb, C_, 3 * C_);
    cudaEventRecord(evQkvW, s3);

    // s2: post-attention weight prep (joins before proj GEMM)
    wcvt_kernel<<<(int)(((size_t)C_ * C_ / 8 + 255) / 256), 256, 0, s2>>>(w_proj, wprjb, C_, C_);
    wperm12_kernel<<<dim3((int)(((size_t)C_ * N12I / 8 + 255) / 256), 2), 256, 0, s2>>>(w12_p, w12_d, w12pb, w12db);
    wcvt3_kernel<<<dim3((int)(((size_t)HIDP * C_ / 8 + 255) / 256), 2), 256, 0, s2>>>(w3_p, w3_d, w3pb, w3db);
    bperm_kernel<<<(N12I + 255) / 256, 256, 0, s2>>>(b12_p, b12_d);
    cudaEventRecord(evJoin, s2);

    // ---- critical path on default stream (runs concurrent with s3) ----
    prep_kernel<<<16, 256>>>(c, flags);
    ada_kernel<<<dim3(48, 2), 128>>>(w_ada_p, b_ada_p, w_ada_d, b_ada_d);
    norm_mod2_kernel<<<TOK, 256>>>(x_pixel, x_dino, g_n1p, g_n1d, ada, 0, 1,
                                   xcb, xcb, NT, 0, NT, NP);

    cudaStreamWaitEvent(0, evQkvW, 0);
    EpiParams e1 = {}; e1.mode = 1; e1.bias = b_qkv; e1.qbf = qb; e1.kbf = kb; e1.vbf = vb;
    bf16_gemm_kernel<<<dim3(24, 40), 256, GEMM_SMEM>>>(xcb, xcb, 1 << 30, wqkvb, wqkvb,
                                                       3 * C_, 3 * C_, C_, e1, e1);

    qknorm_rope_kernel<<<dim3(B_ * H_ * NT / 8, 2), 256>>>(qb, kb, g_qn, g_kn);

    attn_mma_kernel<<<dim3(10, 64), 256, ATTN_SMEM>>>(qb, kb, vb, attnb);

    cudaStreamWaitEvent(0, evJoin, 0);

    EpiParams e2 = {}; e2.mode = 2; e2.bias = b_proj; e2.xpix = x_pixel; e2.xdin = x_dino;
    e2.ada = ada; e2.xap = xap; e2.xad = xad;
    bf16_gemm_kernel<<<dim3(8, 40), 256, GEMM_SMEM>>>(attnb, attnb, 1 << 30, wprjb, wprjb,
                                                      C_, C_, C_, e2, e2);

    norm_mod2_kernel<<<TOK, 256>>>(xap, xad, g_n2p, g_n2d, ada, 3, 4,
                                   h2pb, h2db, NP, 0, ND, 0);

    EpiParams e3 = {}; e3.mode = 4; e3.bias = S + OFF_B12P; e3.glout = glpb;
    EpiParams e4 = {}; e4.mode = 4; e4.bias = S + OFF_B12D; e4.glout = gldb;
    bf16_gemm_kernel<<<dim3(43, 40), 256, GEMM_SMEM>>>(h2pb, h2db, 32, w12pb, w12db,
                                                       N12I, N12I, C_, e3, e4);

    EpiParams e5 = {}; e5.mode = 3; e5.bias = b3_p; e5.resid = xap;
    e5.gate = ada + 5 * C_; e5.rpb = NP; e5.out = out;
    EpiParams e6 = {}; e6.mode = 3; e6.bias = b3_d; e6.resid = xad;
    e6.gate = ada + 4 * 6144 + 5 * C_; e6.rpb = ND; e6.out = out + (size_t)PTOK * C_;
    bf16_gemm_kernel<<<dim3(8, 40), 256, GEMM_SMEM>>>(glpb, gldb, 32, w3pb, w3db,
                                                      C_, C_, HIDP, e5, e6);

    // ---- release handles so device memory returns to the pre-capture baseline ----
    cudaEventDestroy(evFork);
    cudaEventDestroy(evJoin);
    cudaEventDestroy(evQkvW);
    cudaStreamDestroy(s2);
    cudaStreamDestroy(s3);
}